// round 2
// baseline (speedup 1.0000x reference)
#include <cuda_runtime.h>
#include <cstdint>
#include <cstdio>

#define B_  2
#define N_  4096
#define M_  512
#define D_  2048
#define H_  16
#define DH_ 128

// ---------------- scratch (static device globals; no allocation) ----------------
__device__ int8_t g_xq[(size_t)B_ * N_ * D_];
__device__ float  g_sx[B_ * N_];
__device__ int8_t g_wqq[(size_t)D_ * D_];
__device__ float  g_swq[D_];
__device__ int8_t g_wpq[(size_t)D_ * D_];
__device__ float  g_swp[D_];
__device__ int8_t g_oq[(size_t)B_ * N_ * D_];
__device__ float  g_so[B_ * N_];
__device__ float  g_q[(size_t)B_ * N_ * D_];
__device__ float  g_kv[(size_t)B_ * M_ * 2 * D_];
__device__ float  g_P[(size_t)B_ * H_ * N_ * M_];
__device__ float  g_o[(size_t)B_ * N_ * D_];

// ---------------- per-row symmetric int8 fake-quant (matches jax _qdq) ----------
__global__ void quant_rows_kernel(const float* __restrict__ in, int8_t* __restrict__ outq,
                                  float* __restrict__ scales, int cols)
{
    const int row = blockIdx.x;
    const float* p = in + (size_t)row * cols;
    __shared__ float red[256];
    float mx = 0.0f;
    for (int c = threadIdx.x; c < cols; c += blockDim.x)
        mx = fmaxf(mx, fabsf(p[c]));
    red[threadIdx.x] = mx;
    __syncthreads();
    for (int s = 128; s > 0; s >>= 1) {
        if (threadIdx.x < s)
            red[threadIdx.x] = fmaxf(red[threadIdx.x], red[threadIdx.x + s]);
        __syncthreads();
    }
    // IEEE division by 127.0f to match jnp exactly (NOT reciprocal multiply)
    const float sc = fmaxf(red[0] / 127.0f, 1e-8f);
    if (threadIdx.x == 0) scales[row] = sc;
    int8_t* qo = outq + (size_t)row * cols;
    for (int c = threadIdx.x; c < cols; c += blockDim.x) {
        float v = rintf(p[c] / sc);          // RNE == jnp.round
        v = fminf(127.0f, fmaxf(-127.0f, v));
        qo[c] = (int8_t)v;
    }
}

// ---------------- int8 GEMM: C[r,c] = (sum_k A[r,k]*B[c,k]) * sa[r]*sb[c] + bias[c]
// A: [rowsA, K] int8 row-major, B: [colsB, K] int8 row-major (both K-contiguous)
__global__ void gemm_s8_kernel(const int8_t* __restrict__ A, const int8_t* __restrict__ Bm,
                               const float* __restrict__ sa, const float* __restrict__ sb,
                               const float* __restrict__ bias, float* __restrict__ C,
                               int colsB, int Kw /* K/4 words */)
{
    __shared__ int As[128][17];
    __shared__ int Bs[128][17];
    const int tid = threadIdx.x;
    const int tx = tid & 15, ty = tid >> 4;
    const int r0 = blockIdx.y * 128;
    const int c0 = blockIdx.x * 128;
    const int* Aw = (const int*)A;
    const int* Bw = (const int*)Bm;
    int acc[8][8] = {};
    for (int kc = 0; kc < Kw; kc += 16) {
#pragma unroll
        for (int l = 0; l < 8; l++) {
            int idx = tid + l * 256;
            int r = idx >> 4, c = idx & 15;
            As[r][c] = Aw[(size_t)(r0 + r) * Kw + kc + c];
            Bs[r][c] = Bw[(size_t)(c0 + r) * Kw + kc + c];
        }
        __syncthreads();
#pragma unroll
        for (int kk = 0; kk < 16; kk++) {
            int a[8], b[8];
#pragma unroll
            for (int i = 0; i < 8; i++) a[i] = As[ty * 8 + i][kk];
#pragma unroll
            for (int j = 0; j < 8; j++) b[j] = Bs[tx * 8 + j][kk];
#pragma unroll
            for (int i = 0; i < 8; i++)
#pragma unroll
                for (int j = 0; j < 8; j++)
                    acc[i][j] = __dp4a(a[i], b[j], acc[i][j]);
        }
        __syncthreads();
    }
#pragma unroll
    for (int i = 0; i < 8; i++) {
        const int r = r0 + ty * 8 + i;
        const float sr = sa[r];
#pragma unroll
        for (int j = 0; j < 8; j++) {
            const int c = c0 + tx * 8 + j;
            C[(size_t)r * colsB + c] = (float)acc[i][j] * sr * sb[c] + bias[c];
        }
    }
}

// ---------------- fp32 GEMM: C[r,c] = sum_k A[r,k]*B[c,k] + bias[c] -------------
__global__ void gemm_f32_kernel(const float* __restrict__ A, const float* __restrict__ Bm,
                                const float* __restrict__ bias, float* __restrict__ C,
                                int colsB, int K)
{
    __shared__ float As[128][17];
    __shared__ float Bs[128][17];
    const int tid = threadIdx.x;
    const int tx = tid & 15, ty = tid >> 4;
    const int r0 = blockIdx.y * 128;
    const int c0 = blockIdx.x * 128;
    float acc[8][8] = {};
    for (int kc = 0; kc < K; kc += 16) {
#pragma unroll
        for (int l = 0; l < 8; l++) {
            int idx = tid + l * 256;
            int r = idx >> 4, c = idx & 15;
            As[r][c] = A[(size_t)(r0 + r) * K + kc + c];
            Bs[r][c] = Bm[(size_t)(c0 + r) * K + kc + c];
        }
        __syncthreads();
#pragma unroll
        for (int kk = 0; kk < 16; kk++) {
            float a[8], b[8];
#pragma unroll
            for (int i = 0; i < 8; i++) a[i] = As[ty * 8 + i][kk];
#pragma unroll
            for (int j = 0; j < 8; j++) b[j] = Bs[tx * 8 + j][kk];
#pragma unroll
            for (int i = 0; i < 8; i++)
#pragma unroll
                for (int j = 0; j < 8; j++)
                    acc[i][j] = fmaf(a[i], b[j], acc[i][j]);
        }
        __syncthreads();
    }
#pragma unroll
    for (int i = 0; i < 8; i++) {
        const int r = r0 + ty * 8 + i;
#pragma unroll
        for (int j = 0; j < 8; j++) {
            const int c = c0 + tx * 8 + j;
            C[(size_t)r * colsB + c] = acc[i][j] + bias[c];
        }
    }
}

// ---------------- attention: scores + softmax (full M=512 row in smem) ----------
// grid (N/64, H, B), 256 threads. smem: Sq[64][132] | Sk[64][132] | Ss[64][512]
#define SQ_STRIDE 132
#define ATTN_SMEM_FLOATS (64 * SQ_STRIDE * 2 + 64 * 512)

__global__ void attn_softmax_kernel(const float* __restrict__ q, const float* __restrict__ kv,
                                    float* __restrict__ P)
{
    extern __shared__ float sm[];
    float* Sq = sm;
    float* Sk = sm + 64 * SQ_STRIDE;
    float* Ss = sm + 64 * SQ_STRIDE * 2;
    const int b = blockIdx.z, h = blockIdx.y, n0 = blockIdx.x * 64;
    const int tid = threadIdx.x;
    const int ty = tid >> 4, tx = tid & 15;
    const float scale = 0.08838834764831845f; // 1/sqrt(128)

    for (int idx = tid; idx < 64 * DH_; idx += 256) {
        int r = idx >> 7, d = idx & 127;
        Sq[r * SQ_STRIDE + d] = q[((size_t)(b * N_ + n0 + r)) * D_ + h * DH_ + d];
    }

    for (int mc = 0; mc < M_ / 64; mc++) {
        for (int idx = tid; idx < 64 * DH_; idx += 256) {
            int r = idx >> 7, d = idx & 127;
            Sk[r * SQ_STRIDE + d] = kv[((size_t)(b * M_ + mc * 64 + r)) * (2 * D_) + h * DH_ + d];
        }
        __syncthreads();
        float acc[4][4] = {};
#pragma unroll 8
        for (int d = 0; d < DH_; d += 4) {
            float4 qa[4], kb[4];
#pragma unroll
            for (int i = 0; i < 4; i++) qa[i] = *(const float4*)&Sq[(ty * 4 + i) * SQ_STRIDE + d];
#pragma unroll
            for (int j = 0; j < 4; j++) kb[j] = *(const float4*)&Sk[(tx * 4 + j) * SQ_STRIDE + d];
#pragma unroll
            for (int i = 0; i < 4; i++)
#pragma unroll
                for (int j = 0; j < 4; j++) {
                    acc[i][j] = fmaf(qa[i].x, kb[j].x, acc[i][j]);
                    acc[i][j] = fmaf(qa[i].y, kb[j].y, acc[i][j]);
                    acc[i][j] = fmaf(qa[i].z, kb[j].z, acc[i][j]);
                    acc[i][j] = fmaf(qa[i].w, kb[j].w, acc[i][j]);
                }
        }
#pragma unroll
        for (int i = 0; i < 4; i++)
#pragma unroll
            for (int j = 0; j < 4; j++)
                Ss[(ty * 4 + i) * 512 + mc * 64 + tx * 4 + j] = acc[i][j] * scale;
        __syncthreads();
    }

    // softmax: one warp per row
    const int warp = tid >> 5, lane = tid & 31;
    for (int r = warp; r < 64; r += 8) {
        float mx = -1e30f;
#pragma unroll
        for (int t = 0; t < 16; t++) mx = fmaxf(mx, Ss[r * 512 + lane + t * 32]);
#pragma unroll
        for (int o = 16; o; o >>= 1) mx = fmaxf(mx, __shfl_xor_sync(0xffffffffu, mx, o));
        float e[16], sum = 0.0f;
#pragma unroll
        for (int t = 0; t < 16; t++) {
            e[t] = expf(Ss[r * 512 + lane + t * 32] - mx);
            sum += e[t];
        }
#pragma unroll
        for (int o = 16; o; o >>= 1) sum += __shfl_xor_sync(0xffffffffu, sum, o);
        const size_t base = (((size_t)(b * H_ + h)) * N_ + n0 + r) * M_;
#pragma unroll
        for (int t = 0; t < 16; t++) P[base + lane + t * 32] = e[t] / sum;
    }
}

// ---------------- O = P @ V : grid (N/64, H, B), 256 threads --------------------
__global__ void pv_kernel(const float* __restrict__ P, const float* __restrict__ kv,
                          float* __restrict__ o)
{
    __shared__ float Sp[64][65];
    __shared__ float Sv[64][SQ_STRIDE];
    const int b = blockIdx.z, h = blockIdx.y, n0 = blockIdx.x * 64;
    const int tid = threadIdx.x;
    const int ty = tid >> 4, tx = tid & 15;
    float acc[4][8] = {};

    for (int mc = 0; mc < M_ / 64; mc++) {
        for (int idx = tid; idx < 64 * 64; idx += 256) {
            int r = idx >> 6, c = idx & 63;
            Sp[r][c] = P[(((size_t)(b * H_ + h)) * N_ + n0 + r) * M_ + mc * 64 + c];
        }
        for (int idx = tid; idx < 64 * DH_; idx += 256) {
            int r = idx >> 7, d = idx & 127;
            Sv[r][d] = kv[((size_t)(b * M_ + mc * 64 + r)) * (2 * D_) + D_ + h * DH_ + d];
        }
        __syncthreads();
#pragma unroll 16
        for (int m = 0; m < 64; m++) {
            float pv[4];
#pragma unroll
            for (int i = 0; i < 4; i++) pv[i] = Sp[ty * 4 + i][m];
            const float4 v0 = *(const float4*)&Sv[m][tx * 8];
            const float4 v1 = *(const float4*)&Sv[m][tx * 8 + 4];
#pragma unroll
            for (int i = 0; i < 4; i++) {
                acc[i][0] = fmaf(pv[i], v0.x, acc[i][0]);
                acc[i][1] = fmaf(pv[i], v0.y, acc[i][1]);
                acc[i][2] = fmaf(pv[i], v0.z, acc[i][2]);
                acc[i][3] = fmaf(pv[i], v0.w, acc[i][3]);
                acc[i][4] = fmaf(pv[i], v1.x, acc[i][4]);
                acc[i][5] = fmaf(pv[i], v1.y, acc[i][5]);
                acc[i][6] = fmaf(pv[i], v1.z, acc[i][6]);
                acc[i][7] = fmaf(pv[i], v1.w, acc[i][7]);
            }
        }
        __syncthreads();
    }
#pragma unroll
    for (int i = 0; i < 4; i++)
#pragma unroll
        for (int j = 0; j < 8; j++)
            o[((size_t)(b * N_ + n0 + ty * 4 + i)) * D_ + h * DH_ + tx * 8 + j] = acc[i][j];
}

// ---------------- launch --------------------------------------------------------
extern "C" void kernel_launch(void* const* d_in, const int* in_sizes, int n_in,
                              void* d_out, int out_size)
{
    const float* x    = (const float*)d_in[0];
    const float* cond = (const float*)d_in[1];
    const float* wq   = (const float*)d_in[2];
    const float* bq   = (const float*)d_in[3];
    const float* wkv  = (const float*)d_in[4];
    const float* bkv  = (const float*)d_in[5];
    const float* wp   = (const float*)d_in[6];
    const float* bp   = (const float*)d_in[7];
    float* out = (float*)d_out;

    void *p_xq, *p_sx, *p_wqq, *p_swq, *p_wpq, *p_swp, *p_oq, *p_so, *p_q, *p_kv, *p_P, *p_o;
    cudaGetSymbolAddress(&p_xq, g_xq);   cudaGetSymbolAddress(&p_sx, g_sx);
    cudaGetSymbolAddress(&p_wqq, g_wqq); cudaGetSymbolAddress(&p_swq, g_swq);
    cudaGetSymbolAddress(&p_wpq, g_wpq); cudaGetSymbolAddress(&p_swp, g_swp);
    cudaGetSymbolAddress(&p_oq, g_oq);   cudaGetSymbolAddress(&p_so, g_so);
    cudaGetSymbolAddress(&p_q, g_q);     cudaGetSymbolAddress(&p_kv, g_kv);
    cudaGetSymbolAddress(&p_P, g_P);     cudaGetSymbolAddress(&p_o, g_o);

    const int attn_smem = ATTN_SMEM_FLOATS * sizeof(float); // ~194 KB
    cudaFuncSetAttribute(attn_softmax_kernel, cudaFuncAttributeMaxDynamicSharedMemorySize, attn_smem);

    // 1) quantize x, wq, wp
    quant_rows_kernel<<<B_ * N_, 256>>>(x,  (int8_t*)p_xq,  (float*)p_sx,  D_);
    quant_rows_kernel<<<D_,      256>>>(wq, (int8_t*)p_wqq, (float*)p_swq, D_);
    quant_rows_kernel<<<D_,      256>>>(wp, (int8_t*)p_wpq, (float*)p_swp, D_);

    // 2) q projection: exact int8 GEMM + scale/bias epilogue
    {
        dim3 grid(D_ / 128, (B_ * N_) / 128);
        gemm_s8_kernel<<<grid, 256>>>((const int8_t*)p_xq, (const int8_t*)p_wqq,
                                      (const float*)p_sx, (const float*)p_swq,
                                      bq, (float*)p_q, D_, D_ / 4);
    }

    // 3) kv projection: fp32 GEMM
    {
        dim3 grid((2 * D_) / 128, (B_ * M_) / 128);
        gemm_f32_kernel<<<grid, 256>>>(cond, wkv, bkv, (float*)p_kv, 2 * D_, D_);
    }

    // 4) attention scores + softmax
    {
        dim3 grid(N_ / 64, H_, B_);
        attn_softmax_kernel<<<grid, 256, attn_smem>>>((const float*)p_q, (const float*)p_kv,
                                                      (float*)p_P);
    }

    // 5) O = P @ V
    {
        dim3 grid(N_ / 64, H_, B_);
        pv_kernel<<<grid, 256>>>((const float*)p_P, (const float*)p_kv, (float*)p_o);
    }

    // 6) re-quantize attention output per token
    quant_rows_kernel<<<B_ * N_, 256>>>((const float*)p_o, (int8_t*)p_oq, (float*)p_so, D_);

    // 7) output projection: exact int8 GEMM + scale/bias epilogue -> d_out
    {
        dim3 grid(D_ / 128, (B_ * N_) / 128);
        gemm_s8_kernel<<<grid, 256>>>((const int8_t*)p_oq, (const int8_t*)p_wpq,
                                      (const float*)p_so, (const float*)p_swp,
                                      bp, out, D_, D_ / 4);
    }
}

// round 4
// speedup vs baseline: 1.1122x; 1.1122x over previous
#include <cuda_runtime.h>
#include <cstdint>

#define B_  2
#define N_  4096
#define M_  512
#define D_  2048
#define H_  16
#define DH_ 128

// ================= scratch ======================================================
__device__ int8_t g_xq[(size_t)B_ * N_ * D_];
__device__ float  g_sx[B_ * N_];
__device__ int8_t g_wqq[(size_t)D_ * D_];
__device__ float  g_swq[D_];
__device__ int8_t g_wpq[(size_t)D_ * D_];
__device__ float  g_swp[D_];
__device__ int8_t g_oq[(size_t)B_ * N_ * D_];
__device__ float  g_so[B_ * N_];
__device__ float  g_q[(size_t)B_ * N_ * D_];
__device__ float  g_kv[(size_t)B_ * M_ * 2 * D_];
__device__ float  g_o[(size_t)B_ * N_ * D_];

// ================= per-row int8 fake-quant (matches jax _qdq exactly) ===========
__global__ void quant_rows_kernel(const float* __restrict__ in, int8_t* __restrict__ outq,
                                  float* __restrict__ scales, int cols)
{
    const int row = blockIdx.x;
    const float* p = in + (size_t)row * cols;
    __shared__ float red[256];
    float mx = 0.0f;
    for (int c = threadIdx.x * 4; c < cols; c += blockDim.x * 4) {
        float4 v = *(const float4*)&p[c];
        mx = fmaxf(mx, fmaxf(fmaxf(fabsf(v.x), fabsf(v.y)), fmaxf(fabsf(v.z), fabsf(v.w))));
    }
    red[threadIdx.x] = mx;
    __syncthreads();
    for (int s = 128; s > 0; s >>= 1) {
        if (threadIdx.x < s)
            red[threadIdx.x] = fmaxf(red[threadIdx.x], red[threadIdx.x + s]);
        __syncthreads();
    }
    const float sc = fmaxf(red[0] / 127.0f, 1e-8f);   // IEEE div matches jnp
    if (threadIdx.x == 0) scales[row] = sc;
    char4* qo = (char4*)(outq + (size_t)row * cols);
    for (int c = threadIdx.x * 4; c < cols; c += blockDim.x * 4) {
        float4 v = *(const float4*)&p[c];
        char4 q;
        q.x = (int8_t)fminf(127.0f, fmaxf(-127.0f, rintf(v.x / sc)));  // RNE == jnp.round
        q.y = (int8_t)fminf(127.0f, fmaxf(-127.0f, rintf(v.y / sc)));
        q.z = (int8_t)fminf(127.0f, fmaxf(-127.0f, rintf(v.z / sc)));
        q.w = (int8_t)fminf(127.0f, fmaxf(-127.0f, rintf(v.w / sc)));
        qo[c >> 2] = q;
    }
}

// ================= int8 tensor-core GEMM (mma.sync m16n8k32) ====================
// C[r,c] = (sum_k A[r,k]*B[c,k]) * sa[r]*sb[c] + bias[c]
// A: [rowsA,K] int8 row-major; B: [colsB,K] int8 row-major (K contiguous = mma col-major B).
// Tile 128x128, BK=64 bytes. 8 warps: 2(m) x 4(n), each warp 64x32.
#define ASTRIDE 20   // words per smem row (64B data + 16B pad): 20*g mod 32 -> conflict-free

__device__ __forceinline__ void mma_s8(int* c, int a0, int a1, int a2, int a3, int b0, int b1)
{
    asm volatile(
        "mma.sync.aligned.m16n8k32.row.col.s32.s8.s8.s32 "
        "{%0,%1,%2,%3}, {%4,%5,%6,%7}, {%8,%9}, {%0,%1,%2,%3};"
        : "+r"(c[0]), "+r"(c[1]), "+r"(c[2]), "+r"(c[3])
        : "r"(a0), "r"(a1), "r"(a2), "r"(a3), "r"(b0), "r"(b1));
}

__global__ __launch_bounds__(256, 2) void gemm_s8_imma_kernel(
    const int8_t* __restrict__ A, const int8_t* __restrict__ Bm,
    const float* __restrict__ sa, const float* __restrict__ sbv,
    const float* __restrict__ bias, float* __restrict__ C, int colsB, int K)
{
    __shared__ int As[2][128 * ASTRIDE];
    __shared__ int Bs[2][128 * ASTRIDE];
    const int tid = threadIdx.x, lane = tid & 31, wid = tid >> 5;
    const int wm = wid & 1, wn = wid >> 1;           // warp grid 2x4
    const int g = lane >> 2, tg = lane & 3;          // groupID, thread-in-group
    const int r0 = blockIdx.y * 128, c0 = blockIdx.x * 128;
    const int Kw = K >> 2;                           // K in words
    const int* Ag = (const int*)A;
    const int* Bg = (const int*)Bm;

    int acc[4][4][4] = {};                           // [m-tile][n-tile][c-frag]

    const int ldrow = tid >> 2, ldc4 = (tid & 3) * 4; // 16B per thread, 2 passes/matrix
    const int nt = K / 64;

    // prologue: tile 0 -> buf 0
    {
        uint4 va0 = *(const uint4*)&Ag[(size_t)(r0 + ldrow) * Kw + ldc4];
        uint4 va1 = *(const uint4*)&Ag[(size_t)(r0 + 64 + ldrow) * Kw + ldc4];
        uint4 vb0 = *(const uint4*)&Bg[(size_t)(c0 + ldrow) * Kw + ldc4];
        uint4 vb1 = *(const uint4*)&Bg[(size_t)(c0 + 64 + ldrow) * Kw + ldc4];
        *(uint4*)&As[0][ldrow * ASTRIDE + ldc4] = va0;
        *(uint4*)&As[0][(64 + ldrow) * ASTRIDE + ldc4] = va1;
        *(uint4*)&Bs[0][ldrow * ASTRIDE + ldc4] = vb0;
        *(uint4*)&Bs[0][(64 + ldrow) * ASTRIDE + ldc4] = vb1;
    }
    __syncthreads();

    for (int t = 0; t < nt; t++) {
        const int buf = t & 1;
        const bool more = (t + 1) < nt;
        uint4 va0, va1, vb0, vb1;
        if (more) {
            const int kw = (t + 1) * 16 + ldc4;
            va0 = *(const uint4*)&Ag[(size_t)(r0 + ldrow) * Kw + kw];
            va1 = *(const uint4*)&Ag[(size_t)(r0 + 64 + ldrow) * Kw + kw];
            vb0 = *(const uint4*)&Bg[(size_t)(c0 + ldrow) * Kw + kw];
            vb1 = *(const uint4*)&Bg[(size_t)(c0 + 64 + ldrow) * Kw + kw];
        }
#pragma unroll
        for (int ks = 0; ks < 2; ks++) {
            const int kw = ks * 8;
            int bf[4][2];
#pragma unroll
            for (int n = 0; n < 4; n++) {
                const int col = wn * 32 + n * 8 + g;
                bf[n][0] = Bs[buf][col * ASTRIDE + kw + tg];
                bf[n][1] = Bs[buf][col * ASTRIDE + kw + tg + 4];
            }
#pragma unroll
            for (int m = 0; m < 4; m++) {
                const int row = wm * 64 + m * 16;
                const int a0 = As[buf][(row + g) * ASTRIDE + kw + tg];
                const int a1 = As[buf][(row + 8 + g) * ASTRIDE + kw + tg];
                const int a2 = As[buf][(row + g) * ASTRIDE + kw + tg + 4];
                const int a3 = As[buf][(row + 8 + g) * ASTRIDE + kw + tg + 4];
#pragma unroll
                for (int n = 0; n < 4; n++)
                    mma_s8(acc[m][n], a0, a1, a2, a3, bf[n][0], bf[n][1]);
            }
        }
        __syncthreads();
        if (more) {
            *(uint4*)&As[buf ^ 1][ldrow * ASTRIDE + ldc4] = va0;
            *(uint4*)&As[buf ^ 1][(64 + ldrow) * ASTRIDE + ldc4] = va1;
            *(uint4*)&Bs[buf ^ 1][ldrow * ASTRIDE + ldc4] = vb0;
            *(uint4*)&Bs[buf ^ 1][(64 + ldrow) * ASTRIDE + ldc4] = vb1;
            __syncthreads();
        }
    }

    // epilogue: c0,c1 -> row g; c2,c3 -> row g+8; cols 2*tg, 2*tg+1
#pragma unroll
    for (int m = 0; m < 4; m++) {
#pragma unroll
        for (int half = 0; half < 2; half++) {
            const int r = r0 + wm * 64 + m * 16 + g + half * 8;
            const float sr = sa[r];
#pragma unroll
            for (int n = 0; n < 4; n++) {
                const int c = c0 + wn * 32 + n * 8 + tg * 2;
                float2 v;
                v.x = (float)acc[m][n][half * 2 + 0] * sr * sbv[c] + bias[c];
                v.y = (float)acc[m][n][half * 2 + 1] * sr * sbv[c + 1] + bias[c + 1];
                *(float2*)&C[(size_t)r * colsB + c] = v;
            }
        }
    }
}

// ================= fp32 GEMM (kv projection) ====================================
__global__ void gemm_f32_kernel(const float* __restrict__ A, const float* __restrict__ Bm,
                                const float* __restrict__ bias, float* __restrict__ C,
                                int colsB, int K)
{
    __shared__ float As[128][17];
    __shared__ float Bs[128][17];
    const int tid = threadIdx.x;
    const int tx = tid & 15, ty = tid >> 4;
    const int r0 = blockIdx.y * 128;
    const int c0 = blockIdx.x * 128;
    float acc[8][8] = {};
    for (int kc = 0; kc < K; kc += 16) {
#pragma unroll
        for (int l = 0; l < 8; l++) {
            int idx = tid + l * 256;
            int r = idx >> 4, c = idx & 15;
            As[r][c] = A[(size_t)(r0 + r) * K + kc + c];
            Bs[r][c] = Bm[(size_t)(c0 + r) * K + kc + c];
        }
        __syncthreads();
#pragma unroll
        for (int kk = 0; kk < 16; kk++) {
            float a[8], b[8];
#pragma unroll
            for (int i = 0; i < 8; i++) a[i] = As[ty * 8 + i][kk];
#pragma unroll
            for (int j = 0; j < 8; j++) b[j] = Bs[tx * 8 + j][kk];
#pragma unroll
            for (int i = 0; i < 8; i++)
#pragma unroll
                for (int j = 0; j < 8; j++)
                    acc[i][j] = fmaf(a[i], b[j], acc[i][j]);
        }
        __syncthreads();
    }
#pragma unroll
    for (int i = 0; i < 8; i++) {
        const int r = r0 + ty * 8 + i;
#pragma unroll
        for (int j = 0; j < 8; j++) {
            const int c = c0 + tx * 8 + j;
            C[(size_t)r * colsB + c] = acc[i][j] + bias[c];
        }
    }
}

// ================= fused attention: scores + softmax + PV =======================
// grid (N/64, H, B), 256 threads. smem: Sq[64*132] | Skv[64*132] | Ss[64*512]
#define SQ_STRIDE 132
#define ATTN_SMEM_FLOATS (64 * SQ_STRIDE * 2 + 64 * 512)

__global__ void attn_fused_kernel(const float* __restrict__ q, const float* __restrict__ kv,
                                  float* __restrict__ o)
{
    extern __shared__ float sm[];
    float* Sq = sm;
    float* Skv = sm + 64 * SQ_STRIDE;
    float* Ss = sm + 64 * SQ_STRIDE * 2;
    const int b = blockIdx.z, h = blockIdx.y, n0 = blockIdx.x * 64;
    const int tid = threadIdx.x;
    const int ty = tid >> 4, tx = tid & 15;
    const float scale = 0.08838834764831845f; // 1/sqrt(128)

    for (int idx = tid; idx < 64 * DH_; idx += 256) {
        int r = idx >> 7, d = idx & 127;
        Sq[r * SQ_STRIDE + d] = q[((size_t)(b * N_ + n0 + r)) * D_ + h * DH_ + d];
    }

    // ---- scores ----
    for (int mc = 0; mc < M_ / 64; mc++) {
        for (int idx = tid; idx < 64 * DH_; idx += 256) {
            int r = idx >> 7, d = idx & 127;
            Skv[r * SQ_STRIDE + d] = kv[((size_t)(b * M_ + mc * 64 + r)) * (2 * D_) + h * DH_ + d];
        }
        __syncthreads();
        float acc[4][4] = {};
#pragma unroll 8
        for (int d = 0; d < DH_; d += 4) {
            float4 qa[4], kb[4];
#pragma unroll
            for (int i = 0; i < 4; i++) qa[i] = *(const float4*)&Sq[(ty * 4 + i) * SQ_STRIDE + d];
#pragma unroll
            for (int j = 0; j < 4; j++) kb[j] = *(const float4*)&Skv[(tx * 4 + j) * SQ_STRIDE + d];
#pragma unroll
            for (int i = 0; i < 4; i++)
#pragma unroll
                for (int j = 0; j < 4; j++) {
                    acc[i][j] = fmaf(qa[i].x, kb[j].x, acc[i][j]);
                    acc[i][j] = fmaf(qa[i].y, kb[j].y, acc[i][j]);
                    acc[i][j] = fmaf(qa[i].z, kb[j].z, acc[i][j]);
                    acc[i][j] = fmaf(qa[i].w, kb[j].w, acc[i][j]);
                }
        }
#pragma unroll
        for (int i = 0; i < 4; i++)
#pragma unroll
            for (int j = 0; j < 4; j++)
                Ss[(ty * 4 + i) * 512 + mc * 64 + tx * 4 + j] = acc[i][j] * scale;
        __syncthreads();
    }

    // ---- softmax in smem (one warp per row) ----
    {
        const int warp = tid >> 5, lane = tid & 31;
        for (int r = warp; r < 64; r += 8) {
            float mx = -1e30f;
#pragma unroll
            for (int t = 0; t < 16; t++) mx = fmaxf(mx, Ss[r * 512 + lane + t * 32]);
#pragma unroll
            for (int off = 16; off; off >>= 1) mx = fmaxf(mx, __shfl_xor_sync(0xffffffffu, mx, off));
            float e[16], sum = 0.0f;
#pragma unroll
            for (int t = 0; t < 16; t++) {
                e[t] = expf(Ss[r * 512 + lane + t * 32] - mx);
                sum += e[t];
            }
#pragma unroll
            for (int off = 16; off; off >>= 1) sum += __shfl_xor_sync(0xffffffffu, sum, off);
#pragma unroll
            for (int t = 0; t < 16; t++) Ss[r * 512 + lane + t * 32] = e[t] / sum;
        }
    }
    __syncthreads();

    // ---- PV (reuse Skv as V tile) ----
    float acc2[4][8] = {};
    for (int mc = 0; mc < M_ / 64; mc++) {
        for (int idx = tid; idx < 64 * DH_; idx += 256) {
            int r = idx >> 7, d = idx & 127;
            Skv[r * SQ_STRIDE + d] = kv[((size_t)(b * M_ + mc * 64 + r)) * (2 * D_) + D_ + h * DH_ + d];
        }
        __syncthreads();
#pragma unroll 16
        for (int m = 0; m < 64; m++) {
            float pv[4];
#pragma unroll
            for (int i = 0; i < 4; i++) pv[i] = Ss[(ty * 4 + i) * 512 + mc * 64 + m];
            const float4 v0 = *(const float4*)&Skv[m * SQ_STRIDE + tx * 8];
            const float4 v1 = *(const float4*)&Skv[m * SQ_STRIDE + tx * 8 + 4];
#pragma unroll
            for (int i = 0; i < 4; i++) {
                acc2[i][0] = fmaf(pv[i], v0.x, acc2[i][0]);
                acc2[i][1] = fmaf(pv[i], v0.y, acc2[i][1]);
                acc2[i][2] = fmaf(pv[i], v0.z, acc2[i][2]);
                acc2[i][3] = fmaf(pv[i], v0.w, acc2[i][3]);
                acc2[i][4] = fmaf(pv[i], v1.x, acc2[i][4]);
                acc2[i][5] = fmaf(pv[i], v1.y, acc2[i][5]);
                acc2[i][6] = fmaf(pv[i], v1.z, acc2[i][6]);
                acc2[i][7] = fmaf(pv[i], v1.w, acc2[i][7]);
            }
        }
        __syncthreads();
    }
#pragma unroll
    for (int i = 0; i < 4; i++)
#pragma unroll
        for (int j = 0; j < 8; j++)
            o[((size_t)(b * N_ + n0 + ty * 4 + i)) * D_ + h * DH_ + tx * 8 + j] = acc2[i][j];
}

// ================= launch =======================================================
extern "C" void kernel_launch(void* const* d_in, const int* in_sizes, int n_in,
                              void* d_out, int out_size)
{
    const float* x    = (const float*)d_in[0];
    const float* cond = (const float*)d_in[1];
    const float* wq   = (const float*)d_in[2];
    const float* bq   = (const float*)d_in[3];
    const float* wkv  = (const float*)d_in[4];
    const float* bkv  = (const float*)d_in[5];
    const float* wp   = (const float*)d_in[6];
    const float* bp   = (const float*)d_in[7];
    float* out = (float*)d_out;

    void *p_xq, *p_sx, *p_wqq, *p_swq, *p_wpq, *p_swp, *p_oq, *p_so, *p_q, *p_kv, *p_o;
    cudaGetSymbolAddress(&p_xq, g_xq);   cudaGetSymbolAddress(&p_sx, g_sx);
    cudaGetSymbolAddress(&p_wqq, g_wqq); cudaGetSymbolAddress(&p_swq, g_swq);
    cudaGetSymbolAddress(&p_wpq, g_wpq); cudaGetSymbolAddress(&p_swp, g_swp);
    cudaGetSymbolAddress(&p_oq, g_oq);   cudaGetSymbolAddress(&p_so, g_so);
    cudaGetSymbolAddress(&p_q, g_q);     cudaGetSymbolAddress(&p_kv, g_kv);
    cudaGetSymbolAddress(&p_o, g_o);

    const int attn_smem = ATTN_SMEM_FLOATS * sizeof(float);
    cudaFuncSetAttribute(attn_fused_kernel, cudaFuncAttributeMaxDynamicSharedMemorySize, attn_smem);

    // 1) quantize x, wq, wp
    quant_rows_kernel<<<B_ * N_, 256>>>(x,  (int8_t*)p_xq,  (float*)p_sx,  D_);
    quant_rows_kernel<<<D_,      256>>>(wq, (int8_t*)p_wqq, (float*)p_swq, D_);
    quant_rows_kernel<<<D_,      256>>>(wp, (int8_t*)p_wpq, (float*)p_swp, D_);

    // 2) q projection: exact int8 tensor-core GEMM
    {
        dim3 grid(D_ / 128, (B_ * N_) / 128);
        gemm_s8_imma_kernel<<<grid, 256>>>((const int8_t*)p_xq, (const int8_t*)p_wqq,
                                           (const float*)p_sx, (const float*)p_swq,
                                           bq, (float*)p_q, D_, D_);
    }

    // 3) kv projection: fp32 GEMM
    {
        dim3 grid((2 * D_) / 128, (B_ * M_) / 128);
        gemm_f32_kernel<<<grid, 256>>>(cond, wkv, bkv, (float*)p_kv, 2 * D_, D_);
    }

    // 4) fused scores + softmax + PV
    {
        dim3 grid(N_ / 64, H_, B_);
        attn_fused_kernel<<<grid, 256, attn_smem>>>((const float*)p_q, (const float*)p_kv,
                                                    (float*)p_o);
    }

    // 5) re-quantize attention output per token
    quant_rows_kernel<<<B_ * N_, 256>>>((const float*)p_o, (int8_t*)p_oq, (float*)p_so, D_);

    // 6) output projection: exact int8 tensor-core GEMM -> d_out
    {
        dim3 grid(D_ / 128, (B_ * N_) / 128);
        gemm_s8_imma_kernel<<<grid, 256>>>((const int8_t*)p_oq, (const int8_t*)p_wpq,
                                           (const float*)p_so, (const float*)p_swp,
                                           bp, out, D_, D_);
    }
}

// round 5
// speedup vs baseline: 1.1145x; 1.0021x over previous
#include <cuda_runtime.h>
#include <cstdint>

#define B_  2
#define N_  4096
#define M_  512
#define D_  2048
#define H_  16
#define DH_ 128

// ================= scratch ======================================================
__device__ int8_t g_xq[(size_t)B_ * N_ * D_];
__device__ float  g_sx[B_ * N_];
__device__ int8_t g_wqq[(size_t)D_ * D_];
__device__ float  g_swq[D_];
__device__ int8_t g_wpq[(size_t)D_ * D_];
__device__ float  g_swp[D_];
__device__ int8_t g_oq[(size_t)B_ * N_ * D_];
__device__ float  g_so[B_ * N_];
__device__ float  g_q[(size_t)B_ * N_ * D_];
__device__ float  g_kv[(size_t)B_ * M_ * 2 * D_];
__device__ float  g_o[(size_t)B_ * N_ * D_];

// ================= per-row int8 fake-quant (matches jax _qdq exactly) ===========
__global__ void quant_rows_kernel(const float* __restrict__ in, int8_t* __restrict__ outq,
                                  float* __restrict__ scales, int cols)
{
    const int row = blockIdx.x;
    const float* p = in + (size_t)row * cols;
    __shared__ float red[256];
    float mx = 0.0f;
    for (int c = threadIdx.x * 4; c < cols; c += blockDim.x * 4) {
        float4 v = *(const float4*)&p[c];
        mx = fmaxf(mx, fmaxf(fmaxf(fabsf(v.x), fabsf(v.y)), fmaxf(fabsf(v.z), fabsf(v.w))));
    }
    red[threadIdx.x] = mx;
    __syncthreads();
    for (int s = 128; s > 0; s >>= 1) {
        if (threadIdx.x < s)
            red[threadIdx.x] = fmaxf(red[threadIdx.x], red[threadIdx.x + s]);
        __syncthreads();
    }
    const float sc = fmaxf(red[0] / 127.0f, 1e-8f);   // IEEE div matches jnp
    if (threadIdx.x == 0) scales[row] = sc;
    char4* qo = (char4*)(outq + (size_t)row * cols);
    for (int c = threadIdx.x * 4; c < cols; c += blockDim.x * 4) {
        float4 v = *(const float4*)&p[c];
        char4 q;
        q.x = (int8_t)fminf(127.0f, fmaxf(-127.0f, rintf(v.x / sc)));  // RNE == jnp.round
        q.y = (int8_t)fminf(127.0f, fmaxf(-127.0f, rintf(v.y / sc)));
        q.z = (int8_t)fminf(127.0f, fmaxf(-127.0f, rintf(v.z / sc)));
        q.w = (int8_t)fminf(127.0f, fmaxf(-127.0f, rintf(v.w / sc)));
        qo[c >> 2] = q;
    }
}

// ================= int8 tensor-core GEMM (mma.sync m16n8k32) ====================
// C[r,c] = (sum_k A[r,k]*B[c,k]) * sa[r]*sb[c] + bias[c]
// A: [rowsA,K] int8 row-major; B: [colsB,K] int8 row-major (K contiguous = mma col-major B).
// Tile 128x128, BK=64 bytes. 8 warps: 2(m) x 4(n), each warp 64x32.
#define ASTRIDE 20   // words per smem row (64B data + 16B pad): 20*g mod 32 -> conflict-free

__device__ __forceinline__ void mma_s8(int* c, int a0, int a1, int a2, int a3, int b0, int b1)
{
    asm volatile(
        "mma.sync.aligned.m16n8k32.row.col.s32.s8.s8.s32 "
        "{%0,%1,%2,%3}, {%4,%5,%6,%7}, {%8,%9}, {%0,%1,%2,%3};"
        : "+r"(c[0]), "+r"(c[1]), "+r"(c[2]), "+r"(c[3])
        : "r"(a0), "r"(a1), "r"(a2), "r"(a3), "r"(b0), "r"(b1));
}

__global__ __launch_bounds__(256, 2) void gemm_s8_imma_kernel(
    const int8_t* __restrict__ A, const int8_t* __restrict__ Bm,
    const float* __restrict__ sa, const float* __restrict__ sbv,
    const float* __restrict__ bias, float* __restrict__ C, int colsB, int K)
{
    __shared__ int As[2][128 * ASTRIDE];
    __shared__ int Bs[2][128 * ASTRIDE];
    const int tid = threadIdx.x, lane = tid & 31, wid = tid >> 5;
    const int wm = wid & 1, wn = wid >> 1;           // warp grid 2x4
    const int g = lane >> 2, tg = lane & 3;          // groupID, thread-in-group
    const int r0 = blockIdx.y * 128, c0 = blockIdx.x * 128;
    const int Kw = K >> 2;                           // K in words
    const int* Ag = (const int*)A;
    const int* Bg = (const int*)Bm;

    int acc[4][4][4] = {};                           // [m-tile][n-tile][c-frag]

    const int ldrow = tid >> 2, ldc4 = (tid & 3) * 4; // 16B per thread, 2 passes/matrix
    const int nt = K / 64;

    // prologue: tile 0 -> buf 0
    {
        uint4 va0 = *(const uint4*)&Ag[(size_t)(r0 + ldrow) * Kw + ldc4];
        uint4 va1 = *(const uint4*)&Ag[(size_t)(r0 + 64 + ldrow) * Kw + ldc4];
        uint4 vb0 = *(const uint4*)&Bg[(size_t)(c0 + ldrow) * Kw + ldc4];
        uint4 vb1 = *(const uint4*)&Bg[(size_t)(c0 + 64 + ldrow) * Kw + ldc4];
        *(uint4*)&As[0][ldrow * ASTRIDE + ldc4] = va0;
        *(uint4*)&As[0][(64 + ldrow) * ASTRIDE + ldc4] = va1;
        *(uint4*)&Bs[0][ldrow * ASTRIDE + ldc4] = vb0;
        *(uint4*)&Bs[0][(64 + ldrow) * ASTRIDE + ldc4] = vb1;
    }
    __syncthreads();

    for (int t = 0; t < nt; t++) {
        const int buf = t & 1;
        const bool more = (t + 1) < nt;
        uint4 va0, va1, vb0, vb1;
        if (more) {
            const int kw = (t + 1) * 16 + ldc4;
            va0 = *(const uint4*)&Ag[(size_t)(r0 + ldrow) * Kw + kw];
            va1 = *(const uint4*)&Ag[(size_t)(r0 + 64 + ldrow) * Kw + kw];
            vb0 = *(const uint4*)&Bg[(size_t)(c0 + ldrow) * Kw + kw];
            vb1 = *(const uint4*)&Bg[(size_t)(c0 + 64 + ldrow) * Kw + kw];
        }
#pragma unroll
        for (int ks = 0; ks < 2; ks++) {
            const int kw = ks * 8;
            int bf[4][2];
#pragma unroll
            for (int n = 0; n < 4; n++) {
                const int col = wn * 32 + n * 8 + g;
                bf[n][0] = Bs[buf][col * ASTRIDE + kw + tg];
                bf[n][1] = Bs[buf][col * ASTRIDE + kw + tg + 4];
            }
#pragma unroll
            for (int m = 0; m < 4; m++) {
                const int row = wm * 64 + m * 16;
                const int a0 = As[buf][(row + g) * ASTRIDE + kw + tg];
                const int a1 = As[buf][(row + 8 + g) * ASTRIDE + kw + tg];
                const int a2 = As[buf][(row + g) * ASTRIDE + kw + tg + 4];
                const int a3 = As[buf][(row + 8 + g) * ASTRIDE + kw + tg + 4];
#pragma unroll
                for (int n = 0; n < 4; n++)
                    mma_s8(acc[m][n], a0, a1, a2, a3, bf[n][0], bf[n][1]);
            }
        }
        __syncthreads();
        if (more) {
            *(uint4*)&As[buf ^ 1][ldrow * ASTRIDE + ldc4] = va0;
            *(uint4*)&As[buf ^ 1][(64 + ldrow) * ASTRIDE + ldc4] = va1;
            *(uint4*)&Bs[buf ^ 1][ldrow * ASTRIDE + ldc4] = vb0;
            *(uint4*)&Bs[buf ^ 1][(64 + ldrow) * ASTRIDE + ldc4] = vb1;
            __syncthreads();
        }
    }

    // epilogue: c0,c1 -> row g; c2,c3 -> row g+8; cols 2*tg, 2*tg+1
#pragma unroll
    for (int m = 0; m < 4; m++) {
#pragma unroll
        for (int half = 0; half < 2; half++) {
            const int r = r0 + wm * 64 + m * 16 + g + half * 8;
            const float sr = sa[r];
#pragma unroll
            for (int n = 0; n < 4; n++) {
                const int c = c0 + wn * 32 + n * 8 + tg * 2;
                float2 v;
                v.x = (float)acc[m][n][half * 2 + 0] * sr * sbv[c] + bias[c];
                v.y = (float)acc[m][n][half * 2 + 1] * sr * sbv[c + 1] + bias[c + 1];
                *(float2*)&C[(size_t)r * colsB + c] = v;
            }
        }
    }
}

// ================= fp32 GEMM (kv projection) ====================================
__global__ void gemm_f32_kernel(const float* __restrict__ A, const float* __restrict__ Bm,
                                const float* __restrict__ bias, float* __restrict__ C,
                                int colsB, int K)
{
    __shared__ float As[128][17];
    __shared__ float Bs[128][17];
    const int tid = threadIdx.x;
    const int tx = tid & 15, ty = tid >> 4;
    const int r0 = blockIdx.y * 128;
    const int c0 = blockIdx.x * 128;
    float acc[8][8] = {};
    for (int kc = 0; kc < K; kc += 16) {
#pragma unroll
        for (int l = 0; l < 8; l++) {
            int idx = tid + l * 256;
            int r = idx >> 4, c = idx & 15;
            As[r][c] = A[(size_t)(r0 + r) * K + kc + c];
            Bs[r][c] = Bm[(size_t)(c0 + r) * K + kc + c];
        }
        __syncthreads();
#pragma unroll
        for (int kk = 0; kk < 16; kk++) {
            float a[8], b[8];
#pragma unroll
            for (int i = 0; i < 8; i++) a[i] = As[ty * 8 + i][kk];
#pragma unroll
            for (int j = 0; j < 8; j++) b[j] = Bs[tx * 8 + j][kk];
#pragma unroll
            for (int i = 0; i < 8; i++)
#pragma unroll
                for (int j = 0; j < 8; j++)
                    acc[i][j] = fmaf(a[i], b[j], acc[i][j]);
        }
        __syncthreads();
    }
#pragma unroll
    for (int i = 0; i < 8; i++) {
        const int r = r0 + ty * 8 + i;
#pragma unroll
        for (int j = 0; j < 8; j++) {
            const int c = c0 + tx * 8 + j;
            C[(size_t)r * colsB + c] = acc[i][j] + bias[c];
        }
    }
}

// ================= fused attention: scores + softmax + PV =======================
// grid (N/64, H, B), 256 threads. smem: Sq[64*132] | Skv[64*132] | Ss[64*512]
#define SQ_STRIDE 132
#define ATTN_SMEM_FLOATS (64 * SQ_STRIDE * 2 + 64 * 512)

__global__ void attn_fused_kernel(const float* __restrict__ q, const float* __restrict__ kv,
                                  float* __restrict__ o)
{
    extern __shared__ float sm[];
    float* Sq = sm;
    float* Skv = sm + 64 * SQ_STRIDE;
    float* Ss = sm + 64 * SQ_STRIDE * 2;
    const int b = blockIdx.z, h = blockIdx.y, n0 = blockIdx.x * 64;
    const int tid = threadIdx.x;
    const int ty = tid >> 4, tx = tid & 15;
    const float scale = 0.08838834764831845f; // 1/sqrt(128)

    for (int idx = tid; idx < 64 * DH_; idx += 256) {
        int r = idx >> 7, d = idx & 127;
        Sq[r * SQ_STRIDE + d] = q[((size_t)(b * N_ + n0 + r)) * D_ + h * DH_ + d];
    }

    // ---- scores ----
    for (int mc = 0; mc < M_ / 64; mc++) {
        for (int idx = tid; idx < 64 * DH_; idx += 256) {
            int r = idx >> 7, d = idx & 127;
            Skv[r * SQ_STRIDE + d] = kv[((size_t)(b * M_ + mc * 64 + r)) * (2 * D_) + h * DH_ + d];
        }
        __syncthreads();
        float acc[4][4] = {};
#pragma unroll 8
        for (int d = 0; d < DH_; d += 4) {
            float4 qa[4], kb[4];
#pragma unroll
            for (int i = 0; i < 4; i++) qa[i] = *(const float4*)&Sq[(ty * 4 + i) * SQ_STRIDE + d];
#pragma unroll
            for (int j = 0; j < 4; j++) kb[j] = *(const float4*)&Skv[(tx * 4 + j) * SQ_STRIDE + d];
#pragma unroll
            for (int i = 0; i < 4; i++)
#pragma unroll
                for (int j = 0; j < 4; j++) {
                    acc[i][j] = fmaf(qa[i].x, kb[j].x, acc[i][j]);
                    acc[i][j] = fmaf(qa[i].y, kb[j].y, acc[i][j]);
                    acc[i][j] = fmaf(qa[i].z, kb[j].z, acc[i][j]);
                    acc[i][j] = fmaf(qa[i].w, kb[j].w, acc[i][j]);
                }
        }
#pragma unroll
        for (int i = 0; i < 4; i++)
#pragma unroll
            for (int j = 0; j < 4; j++)
                Ss[(ty * 4 + i) * 512 + mc * 64 + tx * 4 + j] = acc[i][j] * scale;
        __syncthreads();
    }

    // ---- softmax in smem (one warp per row) ----
    {
        const int warp = tid >> 5, lane = tid & 31;
        for (int r = warp; r < 64; r += 8) {
            float mx = -1e30f;
#pragma unroll
            for (int t = 0; t < 16; t++) mx = fmaxf(mx, Ss[r * 512 + lane + t * 32]);
#pragma unroll
            for (int off = 16; off; off >>= 1) mx = fmaxf(mx, __shfl_xor_sync(0xffffffffu, mx, off));
            float e[16], sum = 0.0f;
#pragma unroll
            for (int t = 0; t < 16; t++) {
                e[t] = expf(Ss[r * 512 + lane + t * 32] - mx);
                sum += e[t];
            }
#pragma unroll
            for (int off = 16; off; off >>= 1) sum += __shfl_xor_sync(0xffffffffu, sum, off);
#pragma unroll
            for (int t = 0; t < 16; t++) Ss[r * 512 + lane + t * 32] = e[t] / sum;
        }
    }
    __syncthreads();

    // ---- PV (reuse Skv as V tile) ----
    float acc2[4][8] = {};
    for (int mc = 0; mc < M_ / 64; mc++) {
        for (int idx = tid; idx < 64 * DH_; idx += 256) {
            int r = idx >> 7, d = idx & 127;
            Skv[r * SQ_STRIDE + d] = kv[((size_t)(b * M_ + mc * 64 + r)) * (2 * D_) + D_ + h * DH_ + d];
        }
        __syncthreads();
#pragma unroll 16
        for (int m = 0; m < 64; m++) {
            float pv[4];
#pragma unroll
            for (int i = 0; i < 4; i++) pv[i] = Ss[(ty * 4 + i) * 512 + mc * 64 + m];
            const float4 v0 = *(const float4*)&Skv[m * SQ_STRIDE + tx * 8];
            const float4 v1 = *(const float4*)&Skv[m * SQ_STRIDE + tx * 8 + 4];
#pragma unroll
            for (int i = 0; i < 4; i++) {
                acc2[i][0] = fmaf(pv[i], v0.x, acc2[i][0]);
                acc2[i][1] = fmaf(pv[i], v0.y, acc2[i][1]);
                acc2[i][2] = fmaf(pv[i], v0.z, acc2[i][2]);
                acc2[i][3] = fmaf(pv[i], v0.w, acc2[i][3]);
                acc2[i][4] = fmaf(pv[i], v1.x, acc2[i][4]);
                acc2[i][5] = fmaf(pv[i], v1.y, acc2[i][5]);
                acc2[i][6] = fmaf(pv[i], v1.z, acc2[i][6]);
                acc2[i][7] = fmaf(pv[i], v1.w, acc2[i][7]);
            }
        }
        __syncthreads();
    }
#pragma unroll
    for (int i = 0; i < 4; i++)
#pragma unroll
        for (int j = 0; j < 8; j++)
            o[((size_t)(b * N_ + n0 + ty * 4 + i)) * D_ + h * DH_ + tx * 8 + j] = acc2[i][j];
}

// ================= launch =======================================================
extern "C" void kernel_launch(void* const* d_in, const int* in_sizes, int n_in,
                              void* d_out, int out_size)
{
    const float* x    = (const float*)d_in[0];
    const float* cond = (const float*)d_in[1];
    const float* wq   = (const float*)d_in[2];
    const float* bq   = (const float*)d_in[3];
    const float* wkv  = (const float*)d_in[4];
    const float* bkv  = (const float*)d_in[5];
    const float* wp   = (const float*)d_in[6];
    const float* bp   = (const float*)d_in[7];
    float* out = (float*)d_out;

    void *p_xq, *p_sx, *p_wqq, *p_swq, *p_wpq, *p_swp, *p_oq, *p_so, *p_q, *p_kv, *p_o;
    cudaGetSymbolAddress(&p_xq, g_xq);   cudaGetSymbolAddress(&p_sx, g_sx);
    cudaGetSymbolAddress(&p_wqq, g_wqq); cudaGetSymbolAddress(&p_swq, g_swq);
    cudaGetSymbolAddress(&p_wpq, g_wpq); cudaGetSymbolAddress(&p_swp, g_swp);
    cudaGetSymbolAddress(&p_oq, g_oq);   cudaGetSymbolAddress(&p_so, g_so);
    cudaGetSymbolAddress(&p_q, g_q);     cudaGetSymbolAddress(&p_kv, g_kv);
    cudaGetSymbolAddress(&p_o, g_o);

    const int attn_smem = ATTN_SMEM_FLOATS * sizeof(float);
    cudaFuncSetAttribute(attn_fused_kernel, cudaFuncAttributeMaxDynamicSharedMemorySize, attn_smem);

    // 1) quantize x, wq, wp
    quant_rows_kernel<<<B_ * N_, 256>>>(x,  (int8_t*)p_xq,  (float*)p_sx,  D_);
    quant_rows_kernel<<<D_,      256>>>(wq, (int8_t*)p_wqq, (float*)p_swq, D_);
    quant_rows_kernel<<<D_,      256>>>(wp, (int8_t*)p_wpq, (float*)p_swp, D_);

    // 2) q projection: exact int8 tensor-core GEMM
    {
        dim3 grid(D_ / 128, (B_ * N_) / 128);
        gemm_s8_imma_kernel<<<grid, 256>>>((const int8_t*)p_xq, (const int8_t*)p_wqq,
                                           (const float*)p_sx, (const float*)p_swq,
                                           bq, (float*)p_q, D_, D_);
    }

    // 3) kv projection: fp32 GEMM
    {
        dim3 grid((2 * D_) / 128, (B_ * M_) / 128);
        gemm_f32_kernel<<<grid, 256>>>(cond, wkv, bkv, (float*)p_kv, 2 * D_, D_);
    }

    // 4) fused scores + softmax + PV
    {
        dim3 grid(N_ / 64, H_, B_);
        attn_fused_kernel<<<grid, 256, attn_smem>>>((const float*)p_q, (const float*)p_kv,
                                                    (float*)p_o);
    }

    // 5) re-quantize attention output per token
    quant_rows_kernel<<<B_ * N_, 256>>>((const float*)p_o, (int8_t*)p_oq, (float*)p_so, D_);

    // 6) output projection: exact int8 tensor-core GEMM -> d_out
    {
        dim3 grid(D_ / 128, (B_ * N_) / 128);
        gemm_s8_imma_kernel<<<grid, 256>>>((const int8_t*)p_oq, (const int8_t*)p_wpq,
                                           (const float*)p_so, (const float*)p_swp,
                                           bp, out, D_, D_);
    }
}

// round 6
// speedup vs baseline: 1.1178x; 1.0029x over previous
#include <cuda_runtime.h>
#include <cstdint>

#define B_  2
#define N_  4096
#define M_  512
#define D_  2048
#define H_  16
#define DH_ 128

// ================= scratch ======================================================
__device__ int8_t g_xq[(size_t)B_ * N_ * D_];
__device__ float  g_sx[B_ * N_];
__device__ int8_t g_wqq[(size_t)D_ * D_];
__device__ float  g_swq[D_];
__device__ int8_t g_wpq[(size_t)D_ * D_];
__device__ float  g_swp[D_];
__device__ int8_t g_oq[(size_t)B_ * N_ * D_];
__device__ float  g_so[B_ * N_];
__device__ float  g_q[(size_t)B_ * N_ * D_];
__device__ float  g_kv[(size_t)B_ * M_ * 2 * D_];
__device__ float  g_o[(size_t)B_ * N_ * D_];

// ================= per-row int8 fake-quant (matches jax _qdq exactly) ===========
__global__ void quant_rows_kernel(const float* __restrict__ in, int8_t* __restrict__ outq,
                                  float* __restrict__ scales, int cols)
{
    const int row = blockIdx.x;
    const float* p = in + (size_t)row * cols;
    __shared__ float red[256];
    float mx = 0.0f;
    for (int c = threadIdx.x * 4; c < cols; c += blockDim.x * 4) {
        float4 v = *(const float4*)&p[c];
        mx = fmaxf(mx, fmaxf(fmaxf(fabsf(v.x), fabsf(v.y)), fmaxf(fabsf(v.z), fabsf(v.w))));
    }
    red[threadIdx.x] = mx;
    __syncthreads();
    for (int s = 128; s > 0; s >>= 1) {
        if (threadIdx.x < s)
            red[threadIdx.x] = fmaxf(red[threadIdx.x], red[threadIdx.x + s]);
        __syncthreads();
    }
    const float sc = fmaxf(red[0] / 127.0f, 1e-8f);   // IEEE div matches jnp
    if (threadIdx.x == 0) scales[row] = sc;
    char4* qo = (char4*)(outq + (size_t)row * cols);
    for (int c = threadIdx.x * 4; c < cols; c += blockDim.x * 4) {
        float4 v = *(const float4*)&p[c];
        char4 q;
        q.x = (int8_t)fminf(127.0f, fmaxf(-127.0f, rintf(v.x / sc)));  // RNE == jnp.round
        q.y = (int8_t)fminf(127.0f, fmaxf(-127.0f, rintf(v.y / sc)));
        q.z = (int8_t)fminf(127.0f, fmaxf(-127.0f, rintf(v.z / sc)));
        q.w = (int8_t)fminf(127.0f, fmaxf(-127.0f, rintf(v.w / sc)));
        qo[c >> 2] = q;
    }
}

// ================= int8 tensor-core GEMM (mma.sync m16n8k32) ====================
// C[r,c] = (sum_k A[r,k]*B[c,k]) * sa[r]*sb[c] + bias[c]
// A: [rowsA,K] int8 row-major; B: [colsB,K] int8 row-major (K contiguous = mma col-major B).
// Tile 128x128, BK=64 bytes. 8 warps: 2(m) x 4(n), each warp 64x32.
#define ASTRIDE 20   // words per smem row (64B data + 16B pad): 20*g mod 32 -> conflict-free

__device__ __forceinline__ void mma_s8(int* c, int a0, int a1, int a2, int a3, int b0, int b1)
{
    asm volatile(
        "mma.sync.aligned.m16n8k32.row.col.s32.s8.s8.s32 "
        "{%0,%1,%2,%3}, {%4,%5,%6,%7}, {%8,%9}, {%0,%1,%2,%3};"
        : "+r"(c[0]), "+r"(c[1]), "+r"(c[2]), "+r"(c[3])
        : "r"(a0), "r"(a1), "r"(a2), "r"(a3), "r"(b0), "r"(b1));
}

__global__ __launch_bounds__(256, 2) void gemm_s8_imma_kernel(
    const int8_t* __restrict__ A, const int8_t* __restrict__ Bm,
    const float* __restrict__ sa, const float* __restrict__ sbv,
    const float* __restrict__ bias, float* __restrict__ C, int colsB, int K)
{
    __shared__ int As[2][128 * ASTRIDE];
    __shared__ int Bs[2][128 * ASTRIDE];
    const int tid = threadIdx.x, lane = tid & 31, wid = tid >> 5;
    const int wm = wid & 1, wn = wid >> 1;           // warp grid 2x4
    const int g = lane >> 2, tg = lane & 3;          // groupID, thread-in-group
    const int r0 = blockIdx.y * 128, c0 = blockIdx.x * 128;
    const int Kw = K >> 2;                           // K in words
    const int* Ag = (const int*)A;
    const int* Bg = (const int*)Bm;

    int acc[4][4][4] = {};                           // [m-tile][n-tile][c-frag]

    const int ldrow = tid >> 2, ldc4 = (tid & 3) * 4; // 16B per thread, 2 passes/matrix
    const int nt = K / 64;

    // prologue: tile 0 -> buf 0
    {
        uint4 va0 = *(const uint4*)&Ag[(size_t)(r0 + ldrow) * Kw + ldc4];
        uint4 va1 = *(const uint4*)&Ag[(size_t)(r0 + 64 + ldrow) * Kw + ldc4];
        uint4 vb0 = *(const uint4*)&Bg[(size_t)(c0 + ldrow) * Kw + ldc4];
        uint4 vb1 = *(const uint4*)&Bg[(size_t)(c0 + 64 + ldrow) * Kw + ldc4];
        *(uint4*)&As[0][ldrow * ASTRIDE + ldc4] = va0;
        *(uint4*)&As[0][(64 + ldrow) * ASTRIDE + ldc4] = va1;
        *(uint4*)&Bs[0][ldrow * ASTRIDE + ldc4] = vb0;
        *(uint4*)&Bs[0][(64 + ldrow) * ASTRIDE + ldc4] = vb1;
    }
    __syncthreads();

    for (int t = 0; t < nt; t++) {
        const int buf = t & 1;
        const bool more = (t + 1) < nt;
        uint4 va0, va1, vb0, vb1;
        if (more) {
            const int kw = (t + 1) * 16 + ldc4;
            va0 = *(const uint4*)&Ag[(size_t)(r0 + ldrow) * Kw + kw];
            va1 = *(const uint4*)&Ag[(size_t)(r0 + 64 + ldrow) * Kw + kw];
            vb0 = *(const uint4*)&Bg[(size_t)(c0 + ldrow) * Kw + kw];
            vb1 = *(const uint4*)&Bg[(size_t)(c0 + 64 + ldrow) * Kw + kw];
        }
#pragma unroll
        for (int ks = 0; ks < 2; ks++) {
            const int kw = ks * 8;
            int bf[4][2];
#pragma unroll
            for (int n = 0; n < 4; n++) {
                const int col = wn * 32 + n * 8 + g;
                bf[n][0] = Bs[buf][col * ASTRIDE + kw + tg];
                bf[n][1] = Bs[buf][col * ASTRIDE + kw + tg + 4];
            }
#pragma unroll
            for (int m = 0; m < 4; m++) {
                const int row = wm * 64 + m * 16;
                const int a0 = As[buf][(row + g) * ASTRIDE + kw + tg];
                const int a1 = As[buf][(row + 8 + g) * ASTRIDE + kw + tg];
                const int a2 = As[buf][(row + g) * ASTRIDE + kw + tg + 4];
                const int a3 = As[buf][(row + 8 + g) * ASTRIDE + kw + tg + 4];
#pragma unroll
                for (int n = 0; n < 4; n++)
                    mma_s8(acc[m][n], a0, a1, a2, a3, bf[n][0], bf[n][1]);
            }
        }
        __syncthreads();
        if (more) {
            *(uint4*)&As[buf ^ 1][ldrow * ASTRIDE + ldc4] = va0;
            *(uint4*)&As[buf ^ 1][(64 + ldrow) * ASTRIDE + ldc4] = va1;
            *(uint4*)&Bs[buf ^ 1][ldrow * ASTRIDE + ldc4] = vb0;
            *(uint4*)&Bs[buf ^ 1][(64 + ldrow) * ASTRIDE + ldc4] = vb1;
            __syncthreads();
        }
    }

    // epilogue: c0,c1 -> row g; c2,c3 -> row g+8; cols 2*tg, 2*tg+1
#pragma unroll
    for (int m = 0; m < 4; m++) {
#pragma unroll
        for (int half = 0; half < 2; half++) {
            const int r = r0 + wm * 64 + m * 16 + g + half * 8;
            const float sr = sa[r];
#pragma unroll
            for (int n = 0; n < 4; n++) {
                const int c = c0 + wn * 32 + n * 8 + tg * 2;
                float2 v;
                v.x = (float)acc[m][n][half * 2 + 0] * sr * sbv[c] + bias[c];
                v.y = (float)acc[m][n][half * 2 + 1] * sr * sbv[c + 1] + bias[c + 1];
                *(float2*)&C[(size_t)r * colsB + c] = v;
            }
        }
    }
}

// ================= fp32 GEMM (kv projection) ====================================
__global__ void gemm_f32_kernel(const float* __restrict__ A, const float* __restrict__ Bm,
                                const float* __restrict__ bias, float* __restrict__ C,
                                int colsB, int K)
{
    __shared__ float As[128][17];
    __shared__ float Bs[128][17];
    const int tid = threadIdx.x;
    const int tx = tid & 15, ty = tid >> 4;
    const int r0 = blockIdx.y * 128;
    const int c0 = blockIdx.x * 128;
    float acc[8][8] = {};
    for (int kc = 0; kc < K; kc += 16) {
#pragma unroll
        for (int l = 0; l < 8; l++) {
            int idx = tid + l * 256;
            int r = idx >> 4, c = idx & 15;
            As[r][c] = A[(size_t)(r0 + r) * K + kc + c];
            Bs[r][c] = Bm[(size_t)(c0 + r) * K + kc + c];
        }
        __syncthreads();
#pragma unroll
        for (int kk = 0; kk < 16; kk++) {
            float a[8], b[8];
#pragma unroll
            for (int i = 0; i < 8; i++) a[i] = As[ty * 8 + i][kk];
#pragma unroll
            for (int j = 0; j < 8; j++) b[j] = Bs[tx * 8 + j][kk];
#pragma unroll
            for (int i = 0; i < 8; i++)
#pragma unroll
                for (int j = 0; j < 8; j++)
                    acc[i][j] = fmaf(a[i], b[j], acc[i][j]);
        }
        __syncthreads();
    }
#pragma unroll
    for (int i = 0; i < 8; i++) {
        const int r = r0 + ty * 8 + i;
#pragma unroll
        for (int j = 0; j < 8; j++) {
            const int c = c0 + tx * 8 + j;
            C[(size_t)r * colsB + c] = acc[i][j] + bias[c];
        }
    }
}

// ================= fused attention: scores + softmax + PV =======================
// grid (N/64, H, B), 256 threads. smem: Sq[64*132] | Skv[64*132] | Ss[64*512]
#define SQ_STRIDE 132
#define ATTN_SMEM_FLOATS (64 * SQ_STRIDE * 2 + 64 * 512)

__global__ void attn_fused_kernel(const float* __restrict__ q, const float* __restrict__ kv,
                                  float* __restrict__ o)
{
    extern __shared__ float sm[];
    float* Sq = sm;
    float* Skv = sm + 64 * SQ_STRIDE;
    float* Ss = sm + 64 * SQ_STRIDE * 2;
    const int b = blockIdx.z, h = blockIdx.y, n0 = blockIdx.x * 64;
    const int tid = threadIdx.x;
    const int ty = tid >> 4, tx = tid & 15;
    const float scale = 0.08838834764831845f; // 1/sqrt(128)

    for (int idx = tid; idx < 64 * DH_; idx += 256) {
        int r = idx >> 7, d = idx & 127;
        Sq[r * SQ_STRIDE + d] = q[((size_t)(b * N_ + n0 + r)) * D_ + h * DH_ + d];
    }

    // ---- scores ----
    for (int mc = 0; mc < M_ / 64; mc++) {
        for (int idx = tid; idx < 64 * DH_; idx += 256) {
            int r = idx >> 7, d = idx & 127;
            Skv[r * SQ_STRIDE + d] = kv[((size_t)(b * M_ + mc * 64 + r)) * (2 * D_) + h * DH_ + d];
        }
        __syncthreads();
        float acc[4][4] = {};
#pragma unroll 8
        for (int d = 0; d < DH_; d += 4) {
            float4 qa[4], kb[4];
#pragma unroll
            for (int i = 0; i < 4; i++) qa[i] = *(const float4*)&Sq[(ty * 4 + i) * SQ_STRIDE + d];
#pragma unroll
            for (int j = 0; j < 4; j++) kb[j] = *(const float4*)&Skv[(tx * 4 + j) * SQ_STRIDE + d];
#pragma unroll
            for (int i = 0; i < 4; i++)
#pragma unroll
                for (int j = 0; j < 4; j++) {
                    acc[i][j] = fmaf(qa[i].x, kb[j].x, acc[i][j]);
                    acc[i][j] = fmaf(qa[i].y, kb[j].y, acc[i][j]);
                    acc[i][j] = fmaf(qa[i].z, kb[j].z, acc[i][j]);
                    acc[i][j] = fmaf(qa[i].w, kb[j].w, acc[i][j]);
                }
        }
#pragma unroll
        for (int i = 0; i < 4; i++)
#pragma unroll
            for (int j = 0; j < 4; j++)
                Ss[(ty * 4 + i) * 512 + mc * 64 + tx * 4 + j] = acc[i][j] * scale;
        __syncthreads();
    }

    // ---- softmax in smem (one warp per row) ----
    {
        const int warp = tid >> 5, lane = tid & 31;
        for (int r = warp; r < 64; r += 8) {
            float mx = -1e30f;
#pragma unroll
            for (int t = 0; t < 16; t++) mx = fmaxf(mx, Ss[r * 512 + lane + t * 32]);
#pragma unroll
            for (int off = 16; off; off >>= 1) mx = fmaxf(mx, __shfl_xor_sync(0xffffffffu, mx, off));
            float e[16], sum = 0.0f;
#pragma unroll
            for (int t = 0; t < 16; t++) {
                e[t] = expf(Ss[r * 512 + lane + t * 32] - mx);
                sum += e[t];
            }
#pragma unroll
            for (int off = 16; off; off >>= 1) sum += __shfl_xor_sync(0xffffffffu, sum, off);
#pragma unroll
            for (int t = 0; t < 16; t++) Ss[r * 512 + lane + t * 32] = e[t] / sum;
        }
    }
    __syncthreads();

    // ---- PV (reuse Skv as V tile) ----
    float acc2[4][8] = {};
    for (int mc = 0; mc < M_ / 64; mc++) {
        for (int idx = tid; idx < 64 * DH_; idx += 256) {
            int r = idx >> 7, d = idx & 127;
            Skv[r * SQ_STRIDE + d] = kv[((size_t)(b * M_ + mc * 64 + r)) * (2 * D_) + D_ + h * DH_ + d];
        }
        __syncthreads();
#pragma unroll 16
        for (int m = 0; m < 64; m++) {
            float pv[4];
#pragma unroll
            for (int i = 0; i < 4; i++) pv[i] = Ss[(ty * 4 + i) * 512 + mc * 64 + m];
            const float4 v0 = *(const float4*)&Skv[m * SQ_STRIDE + tx * 8];
            const float4 v1 = *(const float4*)&Skv[m * SQ_STRIDE + tx * 8 + 4];
#pragma unroll
            for (int i = 0; i < 4; i++) {
                acc2[i][0] = fmaf(pv[i], v0.x, acc2[i][0]);
                acc2[i][1] = fmaf(pv[i], v0.y, acc2[i][1]);
                acc2[i][2] = fmaf(pv[i], v0.z, acc2[i][2]);
                acc2[i][3] = fmaf(pv[i], v0.w, acc2[i][3]);
                acc2[i][4] = fmaf(pv[i], v1.x, acc2[i][4]);
                acc2[i][5] = fmaf(pv[i], v1.y, acc2[i][5]);
                acc2[i][6] = fmaf(pv[i], v1.z, acc2[i][6]);
                acc2[i][7] = fmaf(pv[i], v1.w, acc2[i][7]);
            }
        }
        __syncthreads();
    }
#pragma unroll
    for (int i = 0; i < 4; i++)
#pragma unroll
        for (int j = 0; j < 8; j++)
            o[((size_t)(b * N_ + n0 + ty * 4 + i)) * D_ + h * DH_ + tx * 8 + j] = acc2[i][j];
}

// ================= launch =======================================================
extern "C" void kernel_launch(void* const* d_in, const int* in_sizes, int n_in,
                              void* d_out, int out_size)
{
    const float* x    = (const float*)d_in[0];
    const float* cond = (const float*)d_in[1];
    const float* wq   = (const float*)d_in[2];
    const float* bq   = (const float*)d_in[3];
    const float* wkv  = (const float*)d_in[4];
    const float* bkv  = (const float*)d_in[5];
    const float* wp   = (const float*)d_in[6];
    const float* bp   = (const float*)d_in[7];
    float* out = (float*)d_out;

    void *p_xq, *p_sx, *p_wqq, *p_swq, *p_wpq, *p_swp, *p_oq, *p_so, *p_q, *p_kv, *p_o;
    cudaGetSymbolAddress(&p_xq, g_xq);   cudaGetSymbolAddress(&p_sx, g_sx);
    cudaGetSymbolAddress(&p_wqq, g_wqq); cudaGetSymbolAddress(&p_swq, g_swq);
    cudaGetSymbolAddress(&p_wpq, g_wpq); cudaGetSymbolAddress(&p_swp, g_swp);
    cudaGetSymbolAddress(&p_oq, g_oq);   cudaGetSymbolAddress(&p_so, g_so);
    cudaGetSymbolAddress(&p_q, g_q);     cudaGetSymbolAddress(&p_kv, g_kv);
    cudaGetSymbolAddress(&p_o, g_o);

    const int attn_smem = ATTN_SMEM_FLOATS * sizeof(float);
    cudaFuncSetAttribute(attn_fused_kernel, cudaFuncAttributeMaxDynamicSharedMemorySize, attn_smem);

    // 1) quantize x, wq, wp
    quant_rows_kernel<<<B_ * N_, 256>>>(x,  (int8_t*)p_xq,  (float*)p_sx,  D_);
    quant_rows_kernel<<<D_,      256>>>(wq, (int8_t*)p_wqq, (float*)p_swq, D_);
    quant_rows_kernel<<<D_,      256>>>(wp, (int8_t*)p_wpq, (float*)p_swp, D_);

    // 2) q projection: exact int8 tensor-core GEMM
    {
        dim3 grid(D_ / 128, (B_ * N_) / 128);
        gemm_s8_imma_kernel<<<grid, 256>>>((const int8_t*)p_xq, (const int8_t*)p_wqq,
                                           (const float*)p_sx, (const float*)p_swq,
                                           bq, (float*)p_q, D_, D_);
    }

    // 3) kv projection: fp32 GEMM
    {
        dim3 grid((2 * D_) / 128, (B_ * M_) / 128);
        gemm_f32_kernel<<<grid, 256>>>(cond, wkv, bkv, (float*)p_kv, 2 * D_, D_);
    }

    // 4) fused scores + softmax + PV
    {
        dim3 grid(N_ / 64, H_, B_);
        attn_fused_kernel<<<grid, 256, attn_smem>>>((const float*)p_q, (const float*)p_kv,
                                                    (float*)p_o);
    }

    // 5) re-quantize attention output per token
    quant_rows_kernel<<<B_ * N_, 256>>>((const float*)p_o, (int8_t*)p_oq, (float*)p_so, D_);

    // 6) output projection: exact int8 tensor-core GEMM -> d_out
    {
        dim3 grid(D_ / 128, (B_ * N_) / 128);
        gemm_s8_imma_kernel<<<grid, 256>>>((const int8_t*)p_oq, (const int8_t*)p_wpq,
                                           (const float*)p_so, (const float*)p_swp,
                                           bp, out, D_, D_);
    }
}

// round 7
// speedup vs baseline: 1.1324x; 1.0130x over previous
#include <cuda_runtime.h>
#include <cstdint>

#define B_  2
#define N_  4096
#define M_  512
#define D_  2048
#define H_  16
#define DH_ 128

// ================= scratch ======================================================
__device__ int8_t g_xq[(size_t)B_ * N_ * D_];
__device__ float  g_sx[B_ * N_];
__device__ int8_t g_wqq[(size_t)D_ * D_];
__device__ float  g_swq[D_];
__device__ int8_t g_wpq[(size_t)D_ * D_];
__device__ float  g_swp[D_];
__device__ int8_t g_oq[(size_t)B_ * N_ * D_];
__device__ float  g_so[B_ * N_];
__device__ float  g_q[(size_t)B_ * N_ * D_];
__device__ float  g_kv[(size_t)B_ * M_ * 2 * D_];
__device__ float  g_o[(size_t)B_ * N_ * D_];

// ================= per-row int8 fake-quant (matches jax _qdq exactly) ===========
__global__ void quant_rows_kernel(const float* __restrict__ in, int8_t* __restrict__ outq,
                                  float* __restrict__ scales, int cols)
{
    const int row = blockIdx.x;
    const float* p = in + (size_t)row * cols;
    __shared__ float red[256];
    float mx = 0.0f;
    for (int c = threadIdx.x * 4; c < cols; c += blockDim.x * 4) {
        float4 v = *(const float4*)&p[c];
        mx = fmaxf(mx, fmaxf(fmaxf(fabsf(v.x), fabsf(v.y)), fmaxf(fabsf(v.z), fabsf(v.w))));
    }
    red[threadIdx.x] = mx;
    __syncthreads();
    for (int s = 128; s > 0; s >>= 1) {
        if (threadIdx.x < s)
            red[threadIdx.x] = fmaxf(red[threadIdx.x], red[threadIdx.x + s]);
        __syncthreads();
    }
    const float sc = fmaxf(red[0] / 127.0f, 1e-8f);   // IEEE div matches jnp
    if (threadIdx.x == 0) scales[row] = sc;
    char4* qo = (char4*)(outq + (size_t)row * cols);
    for (int c = threadIdx.x * 4; c < cols; c += blockDim.x * 4) {
        float4 v = *(const float4*)&p[c];
        char4 q;
        q.x = (int8_t)fminf(127.0f, fmaxf(-127.0f, rintf(v.x / sc)));  // RNE == jnp.round
        q.y = (int8_t)fminf(127.0f, fmaxf(-127.0f, rintf(v.y / sc)));
        q.z = (int8_t)fminf(127.0f, fmaxf(-127.0f, rintf(v.z / sc)));
        q.w = (int8_t)fminf(127.0f, fmaxf(-127.0f, rintf(v.w / sc)));
        qo[c >> 2] = q;
    }
}

// ================= int8 tensor-core GEMM (mma.sync m16n8k32) ====================
#define ASTRIDE 20

__device__ __forceinline__ void mma_s8(int* c, int a0, int a1, int a2, int a3, int b0, int b1)
{
    asm volatile(
        "mma.sync.aligned.m16n8k32.row.col.s32.s8.s8.s32 "
        "{%0,%1,%2,%3}, {%4,%5,%6,%7}, {%8,%9}, {%0,%1,%2,%3};"
        : "+r"(c[0]), "+r"(c[1]), "+r"(c[2]), "+r"(c[3])
        : "r"(a0), "r"(a1), "r"(a2), "r"(a3), "r"(b0), "r"(b1));
}

__global__ __launch_bounds__(256, 2) void gemm_s8_imma_kernel(
    const int8_t* __restrict__ A, const int8_t* __restrict__ Bm,
    const float* __restrict__ sa, const float* __restrict__ sbv,
    const float* __restrict__ bias, float* __restrict__ C, int colsB, int K)
{
    __shared__ int As[2][128 * ASTRIDE];
    __shared__ int Bs[2][128 * ASTRIDE];
    const int tid = threadIdx.x, lane = tid & 31, wid = tid >> 5;
    const int wm = wid & 1, wn = wid >> 1;
    const int g = lane >> 2, tg = lane & 3;
    const int r0 = blockIdx.y * 128, c0 = blockIdx.x * 128;
    const int Kw = K >> 2;
    const int* Ag = (const int*)A;
    const int* Bg = (const int*)Bm;

    int acc[4][4][4] = {};
    const int ldrow = tid >> 2, ldc4 = (tid & 3) * 4;
    const int nt = K / 64;

    {
        uint4 va0 = *(const uint4*)&Ag[(size_t)(r0 + ldrow) * Kw + ldc4];
        uint4 va1 = *(const uint4*)&Ag[(size_t)(r0 + 64 + ldrow) * Kw + ldc4];
        uint4 vb0 = *(const uint4*)&Bg[(size_t)(c0 + ldrow) * Kw + ldc4];
        uint4 vb1 = *(const uint4*)&Bg[(size_t)(c0 + 64 + ldrow) * Kw + ldc4];
        *(uint4*)&As[0][ldrow * ASTRIDE + ldc4] = va0;
        *(uint4*)&As[0][(64 + ldrow) * ASTRIDE + ldc4] = va1;
        *(uint4*)&Bs[0][ldrow * ASTRIDE + ldc4] = vb0;
        *(uint4*)&Bs[0][(64 + ldrow) * ASTRIDE + ldc4] = vb1;
    }
    __syncthreads();

    for (int t = 0; t < nt; t++) {
        const int buf = t & 1;
        const bool more = (t + 1) < nt;
        uint4 va0, va1, vb0, vb1;
        if (more) {
            const int kw = (t + 1) * 16 + ldc4;
            va0 = *(const uint4*)&Ag[(size_t)(r0 + ldrow) * Kw + kw];
            va1 = *(const uint4*)&Ag[(size_t)(r0 + 64 + ldrow) * Kw + kw];
            vb0 = *(const uint4*)&Bg[(size_t)(c0 + ldrow) * Kw + kw];
            vb1 = *(const uint4*)&Bg[(size_t)(c0 + 64 + ldrow) * Kw + kw];
        }
#pragma unroll
        for (int ks = 0; ks < 2; ks++) {
            const int kw = ks * 8;
            int bf[4][2];
#pragma unroll
            for (int n = 0; n < 4; n++) {
                const int col = wn * 32 + n * 8 + g;
                bf[n][0] = Bs[buf][col * ASTRIDE + kw + tg];
                bf[n][1] = Bs[buf][col * ASTRIDE + kw + tg + 4];
            }
#pragma unroll
            for (int m = 0; m < 4; m++) {
                const int row = wm * 64 + m * 16;
                const int a0 = As[buf][(row + g) * ASTRIDE + kw + tg];
                const int a1 = As[buf][(row + 8 + g) * ASTRIDE + kw + tg];
                const int a2 = As[buf][(row + g) * ASTRIDE + kw + tg + 4];
                const int a3 = As[buf][(row + 8 + g) * ASTRIDE + kw + tg + 4];
#pragma unroll
                for (int n = 0; n < 4; n++)
                    mma_s8(acc[m][n], a0, a1, a2, a3, bf[n][0], bf[n][1]);
            }
        }
        __syncthreads();
        if (more) {
            *(uint4*)&As[buf ^ 1][ldrow * ASTRIDE + ldc4] = va0;
            *(uint4*)&As[buf ^ 1][(64 + ldrow) * ASTRIDE + ldc4] = va1;
            *(uint4*)&Bs[buf ^ 1][ldrow * ASTRIDE + ldc4] = vb0;
            *(uint4*)&Bs[buf ^ 1][(64 + ldrow) * ASTRIDE + ldc4] = vb1;
            __syncthreads();
        }
    }

#pragma unroll
    for (int m = 0; m < 4; m++) {
#pragma unroll
        for (int half = 0; half < 2; half++) {
            const int r = r0 + wm * 64 + m * 16 + g + half * 8;
            const float sr = sa[r];
#pragma unroll
            for (int n = 0; n < 4; n++) {
                const int c = c0 + wn * 32 + n * 8 + tg * 2;
                float2 v;
                v.x = (float)acc[m][n][half * 2 + 0] * sr * sbv[c] + bias[c];
                v.y = (float)acc[m][n][half * 2 + 1] * sr * sbv[c + 1] + bias[c + 1];
                *(float2*)&C[(size_t)r * colsB + c] = v;
            }
        }
    }
}

// ================= fp32 GEMM (kv projection) ====================================
__global__ void gemm_f32_kernel(const float* __restrict__ A, const float* __restrict__ Bm,
                                const float* __restrict__ bias, float* __restrict__ C,
                                int colsB, int K)
{
    __shared__ float As[128][17];
    __shared__ float Bs[128][17];
    const int tid = threadIdx.x;
    const int tx = tid & 15, ty = tid >> 4;
    const int r0 = blockIdx.y * 128;
    const int c0 = blockIdx.x * 128;
    float acc[8][8] = {};
    for (int kc = 0; kc < K; kc += 16) {
#pragma unroll
        for (int l = 0; l < 8; l++) {
            int idx = tid + l * 256;
            int r = idx >> 4, c = idx & 15;
            As[r][c] = A[(size_t)(r0 + r) * K + kc + c];
            Bs[r][c] = Bm[(size_t)(c0 + r) * K + kc + c];
        }
        __syncthreads();
#pragma unroll
        for (int kk = 0; kk < 16; kk++) {
            float a[8], b[8];
#pragma unroll
            for (int i = 0; i < 8; i++) a[i] = As[ty * 8 + i][kk];
#pragma unroll
            for (int j = 0; j < 8; j++) b[j] = Bs[tx * 8 + j][kk];
#pragma unroll
            for (int i = 0; i < 8; i++)
#pragma unroll
                for (int j = 0; j < 8; j++)
                    acc[i][j] = fmaf(a[i], b[j], acc[i][j]);
        }
        __syncthreads();
    }
#pragma unroll
    for (int i = 0; i < 8; i++) {
        const int r = r0 + ty * 8 + i;
#pragma unroll
        for (int j = 0; j < 8; j++) {
            const int c = c0 + tx * 8 + j;
            C[(size_t)r * colsB + c] = acc[i][j] + bias[c];
        }
    }
}

// ================= fused attention: scores + softmax + PV (one batch) ===========
// grid (N/64, H, 1), 256 threads. Pointers pre-offset per batch by host.
#define SQ_STRIDE 132
#define ATTN_SMEM_FLOATS (64 * SQ_STRIDE * 2 + 64 * 512)

__global__ void attn_fused_kernel(const float* __restrict__ q, const float* __restrict__ kv,
                                  float* __restrict__ o)
{
    extern __shared__ float sm[];
    float* Sq = sm;
    float* Skv = sm + 64 * SQ_STRIDE;
    float* Ss = sm + 64 * SQ_STRIDE * 2;
    const int h = blockIdx.y, n0 = blockIdx.x * 64;
    const int tid = threadIdx.x;
    const int ty = tid >> 4, tx = tid & 15;
    const float scale = 0.08838834764831845f; // 1/sqrt(128)

    for (int idx = tid; idx < 64 * DH_; idx += 256) {
        int r = idx >> 7, d = idx & 127;
        Sq[r * SQ_STRIDE + d] = q[((size_t)(n0 + r)) * D_ + h * DH_ + d];
    }

    // ---- scores ----
    for (int mc = 0; mc < M_ / 64; mc++) {
        for (int idx = tid; idx < 64 * DH_; idx += 256) {
            int r = idx >> 7, d = idx & 127;
            Skv[r * SQ_STRIDE + d] = kv[((size_t)(mc * 64 + r)) * (2 * D_) + h * DH_ + d];
        }
        __syncthreads();
        float acc[4][4] = {};
#pragma unroll 8
        for (int d = 0; d < DH_; d += 4) {
            float4 qa[4], kb[4];
#pragma unroll
            for (int i = 0; i < 4; i++) qa[i] = *(const float4*)&Sq[(ty * 4 + i) * SQ_STRIDE + d];
#pragma unroll
            for (int j = 0; j < 4; j++) kb[j] = *(const float4*)&Skv[(tx * 4 + j) * SQ_STRIDE + d];
#pragma unroll
            for (int i = 0; i < 4; i++)
#pragma unroll
                for (int j = 0; j < 4; j++) {
                    acc[i][j] = fmaf(qa[i].x, kb[j].x, acc[i][j]);
                    acc[i][j] = fmaf(qa[i].y, kb[j].y, acc[i][j]);
                    acc[i][j] = fmaf(qa[i].z, kb[j].z, acc[i][j]);
                    acc[i][j] = fmaf(qa[i].w, kb[j].w, acc[i][j]);
                }
        }
#pragma unroll
        for (int i = 0; i < 4; i++)
#pragma unroll
            for (int j = 0; j < 4; j++)
                Ss[(ty * 4 + i) * 512 + mc * 64 + tx * 4 + j] = acc[i][j] * scale;
        __syncthreads();
    }

    // ---- softmax in smem (one warp per row) ----
    {
        const int warp = tid >> 5, lane = tid & 31;
        for (int r = warp; r < 64; r += 8) {
            float mx = -1e30f;
#pragma unroll
            for (int t = 0; t < 16; t++) mx = fmaxf(mx, Ss[r * 512 + lane + t * 32]);
#pragma unroll
            for (int off = 16; off; off >>= 1) mx = fmaxf(mx, __shfl_xor_sync(0xffffffffu, mx, off));
            float e[16], sum = 0.0f;
#pragma unroll
            for (int t = 0; t < 16; t++) {
                e[t] = __expf(Ss[r * 512 + lane + t * 32] - mx);   // MUFU.EX2 path
                sum += e[t];
            }
#pragma unroll
            for (int off = 16; off; off >>= 1) sum += __shfl_xor_sync(0xffffffffu, sum, off);
            const float inv = 1.0f / sum;                          // one div per row
#pragma unroll
            for (int t = 0; t < 16; t++) Ss[r * 512 + lane + t * 32] = e[t] * inv;
        }
    }
    __syncthreads();

    // ---- PV (reuse Skv as V tile) ----
    float acc2[4][8] = {};
    for (int mc = 0; mc < M_ / 64; mc++) {
        for (int idx = tid; idx < 64 * DH_; idx += 256) {
            int r = idx >> 7, d = idx & 127;
            Skv[r * SQ_STRIDE + d] = kv[((size_t)(mc * 64 + r)) * (2 * D_) + D_ + h * DH_ + d];
        }
        __syncthreads();
#pragma unroll 16
        for (int m = 0; m < 64; m++) {
            float pv[4];
#pragma unroll
            for (int i = 0; i < 4; i++) pv[i] = Ss[(ty * 4 + i) * 512 + mc * 64 + m];
            const float4 v0 = *(const float4*)&Skv[m * SQ_STRIDE + tx * 8];
            const float4 v1 = *(const float4*)&Skv[m * SQ_STRIDE + tx * 8 + 4];
#pragma unroll
            for (int i = 0; i < 4; i++) {
                acc2[i][0] = fmaf(pv[i], v0.x, acc2[i][0]);
                acc2[i][1] = fmaf(pv[i], v0.y, acc2[i][1]);
                acc2[i][2] = fmaf(pv[i], v0.z, acc2[i][2]);
                acc2[i][3] = fmaf(pv[i], v0.w, acc2[i][3]);
                acc2[i][4] = fmaf(pv[i], v1.x, acc2[i][4]);
                acc2[i][5] = fmaf(pv[i], v1.y, acc2[i][5]);
                acc2[i][6] = fmaf(pv[i], v1.z, acc2[i][6]);
                acc2[i][7] = fmaf(pv[i], v1.w, acc2[i][7]);
            }
        }
        __syncthreads();
    }
#pragma unroll
    for (int i = 0; i < 4; i++)
#pragma unroll
        for (int j = 0; j < 8; j++)
            o[((size_t)(n0 + ty * 4 + i)) * D_ + h * DH_ + tx * 8 + j] = acc2[i][j];
}

// ================= launch: batch-pipelined multi-stream DAG =====================
extern "C" void kernel_launch(void* const* d_in, const int* in_sizes, int n_in,
                              void* d_out, int out_size)
{
    const float* x    = (const float*)d_in[0];
    const float* cond = (const float*)d_in[1];
    const float* wq   = (const float*)d_in[2];
    const float* bq   = (const float*)d_in[3];
    const float* wkv  = (const float*)d_in[4];
    const float* bkv  = (const float*)d_in[5];
    const float* wp   = (const float*)d_in[6];
    const float* bp   = (const float*)d_in[7];
    float* out = (float*)d_out;

    void *p_xq, *p_sx, *p_wqq, *p_swq, *p_wpq, *p_swp, *p_oq, *p_so, *p_q, *p_kv, *p_o;
    cudaGetSymbolAddress(&p_xq, g_xq);   cudaGetSymbolAddress(&p_sx, g_sx);
    cudaGetSymbolAddress(&p_wqq, g_wqq); cudaGetSymbolAddress(&p_swq, g_swq);
    cudaGetSymbolAddress(&p_wpq, g_wpq); cudaGetSymbolAddress(&p_swp, g_swp);
    cudaGetSymbolAddress(&p_oq, g_oq);   cudaGetSymbolAddress(&p_so, g_so);
    cudaGetSymbolAddress(&p_q, g_q);     cudaGetSymbolAddress(&p_kv, g_kv);
    cudaGetSymbolAddress(&p_o, g_o);

    int8_t* xq  = (int8_t*)p_xq;   float* sx  = (float*)p_sx;
    int8_t* wqq = (int8_t*)p_wqq;  float* swq = (float*)p_swq;
    int8_t* wpq = (int8_t*)p_wpq;  float* swp = (float*)p_swp;
    int8_t* oq  = (int8_t*)p_oq;   float* so  = (float*)p_so;
    float* qb   = (float*)p_q;     float* kvb = (float*)p_kv;
    float* ob   = (float*)p_o;

    // one-time stream/event setup (host-side resources only; no device alloc)
    static cudaStream_t sK = nullptr, sB1 = nullptr;
    static cudaEvent_t eFork, eKV0, eKV1, eQG1, eATTN0, eDONE1;
    if (sK == nullptr) {
        cudaStreamCreateWithFlags(&sK,  cudaStreamNonBlocking);
        cudaStreamCreateWithFlags(&sB1, cudaStreamNonBlocking);
        cudaEventCreateWithFlags(&eFork,  cudaEventDisableTiming);
        cudaEventCreateWithFlags(&eKV0,   cudaEventDisableTiming);
        cudaEventCreateWithFlags(&eKV1,   cudaEventDisableTiming);
        cudaEventCreateWithFlags(&eQG1,   cudaEventDisableTiming);
        cudaEventCreateWithFlags(&eATTN0, cudaEventDisableTiming);
        cudaEventCreateWithFlags(&eDONE1, cudaEventDisableTiming);
    }

    const int attn_smem = ATTN_SMEM_FLOATS * sizeof(float);
    cudaFuncSetAttribute(attn_fused_kernel, cudaFuncAttributeMaxDynamicSharedMemorySize, attn_smem);

    const size_t XB = (size_t)N_ * D_;       // x/q/o per-batch elements
    const size_t KVB = (size_t)M_ * 2 * D_;  // kv per-batch elements

    // ---- fork: kv projection (fp32, FMA pipe) on side stream ----
    cudaEventRecord(eFork, 0);
    cudaStreamWaitEvent(sK, eFork, 0);
    {
        dim3 grid((2 * D_) / 128, M_ / 128);
        gemm_f32_kernel<<<grid, 256, 0, sK>>>(cond, wkv, bkv, kvb, 2 * D_, D_);
        cudaEventRecord(eKV0, sK);
        gemm_f32_kernel<<<grid, 256, 0, sK>>>(cond + (size_t)M_ * D_, wkv, bkv,
                                              kvb + KVB, 2 * D_, D_);
        cudaEventRecord(eKV1, sK);
    }

    // ---- main: quant weights + per-batch x-quant + q-gemm (tensor pipe) ----
    quant_rows_kernel<<<D_, 256>>>(wq, wqq, swq, D_);
    quant_rows_kernel<<<D_, 256>>>(wp, wpq, swp, D_);
    quant_rows_kernel<<<N_, 256>>>(x, xq, sx, D_);
    {
        dim3 grid(D_ / 128, N_ / 128);
        gemm_s8_imma_kernel<<<grid, 256>>>(xq, wqq, sx, swq, bq, qb, D_, D_);
    }
    quant_rows_kernel<<<N_, 256>>>(x + XB, xq + XB, sx + N_, D_);
    {
        dim3 grid(D_ / 128, N_ / 128);
        gemm_s8_imma_kernel<<<grid, 256>>>(xq + XB, wqq, sx + N_, swq, bq, qb + XB, D_, D_);
    }
    cudaEventRecord(eQG1, 0);

    // ---- attn(b0) on main after kv(b0) ----
    cudaStreamWaitEvent(0, eKV0, 0);
    {
        dim3 grid(N_ / 64, H_, 1);
        attn_fused_kernel<<<grid, 256, attn_smem>>>(qb, kvb, ob);
    }
    cudaEventRecord(eATTN0, 0);

    // ---- branch: attn(b1) + epilogue(b1) on sB1 (runs after attn b0; its
    //      tensor-pipe out-gemm overlaps nothing, but b0's out-gemm below
    //      overlaps attn(b1) on the FMA pipe) ----
    cudaStreamWaitEvent(sB1, eQG1, 0);
    cudaStreamWaitEvent(sB1, eKV1, 0);
    cudaStreamWaitEvent(sB1, eATTN0, 0);
    {
        dim3 grid(N_ / 64, H_, 1);
        attn_fused_kernel<<<grid, 256, attn_smem, sB1>>>(qb + XB, kvb + KVB, ob + XB);
    }
    quant_rows_kernel<<<N_, 256, 0, sB1>>>(ob + XB, oq + XB, so + N_, D_);
    {
        dim3 grid(D_ / 128, N_ / 128);
        gemm_s8_imma_kernel<<<grid, 256, 0, sB1>>>(oq + XB, wpq, so + N_, swp, bp,
                                                   out + XB, D_, D_);
    }
    cudaEventRecord(eDONE1, sB1);

    // ---- main: epilogue(b0) (tensor pipe) overlaps attn(b1) (FMA pipe) ----
    quant_rows_kernel<<<N_, 256>>>(ob, oq, so, D_);
    {
        dim3 grid(D_ / 128, N_ / 128);
        gemm_s8_imma_kernel<<<grid, 256>>>(oq, wpq, so, swp, bp, out, D_, D_);
    }

    // ---- join ----
    cudaStreamWaitEvent(0, eDONE1, 0);
}

// round 8
// speedup vs baseline: 1.4973x; 1.3223x over previous
#include <cuda_runtime.h>
#include <cstdint>

#define B_  2
#define N_  4096
#define M_  512
#define D_  2048
#define H_  16
#define DH_ 128

// ================= scratch ======================================================
__device__ int8_t g_xq[(size_t)B_ * N_ * D_];
__device__ float  g_sx[B_ * N_];
__device__ int8_t g_wqq[(size_t)D_ * D_];
__device__ float  g_swq[D_];
__device__ int8_t g_wpq[(size_t)D_ * D_];
__device__ float  g_swp[D_];
__device__ int8_t g_oq[(size_t)B_ * N_ * D_];
__device__ float  g_so[B_ * N_];
__device__ float  g_q[(size_t)B_ * N_ * D_];
__device__ float  g_kv[(size_t)B_ * M_ * 2 * D_];
__device__ float  g_o[(size_t)B_ * N_ * D_];

// ================= per-row int8 fake-quant (matches jax _qdq exactly) ===========
__global__ void quant_rows_kernel(const float* __restrict__ in, int8_t* __restrict__ outq,
                                  float* __restrict__ scales, int cols)
{
    const int row = blockIdx.x;
    const float* p = in + (size_t)row * cols;
    __shared__ float red[256];
    float mx = 0.0f;
    for (int c = threadIdx.x * 4; c < cols; c += blockDim.x * 4) {
        float4 v = *(const float4*)&p[c];
        mx = fmaxf(mx, fmaxf(fmaxf(fabsf(v.x), fabsf(v.y)), fmaxf(fabsf(v.z), fabsf(v.w))));
    }
    red[threadIdx.x] = mx;
    __syncthreads();
    for (int s = 128; s > 0; s >>= 1) {
        if (threadIdx.x < s)
            red[threadIdx.x] = fmaxf(red[threadIdx.x], red[threadIdx.x + s]);
        __syncthreads();
    }
    const float sc = fmaxf(red[0] / 127.0f, 1e-8f);   // IEEE div matches jnp
    if (threadIdx.x == 0) scales[row] = sc;
    char4* qo = (char4*)(outq + (size_t)row * cols);
    for (int c = threadIdx.x * 4; c < cols; c += blockDim.x * 4) {
        float4 v = *(const float4*)&p[c];
        char4 q;
        q.x = (int8_t)fminf(127.0f, fmaxf(-127.0f, rintf(v.x / sc)));  // RNE == jnp.round
        q.y = (int8_t)fminf(127.0f, fmaxf(-127.0f, rintf(v.y / sc)));
        q.z = (int8_t)fminf(127.0f, fmaxf(-127.0f, rintf(v.z / sc)));
        q.w = (int8_t)fminf(127.0f, fmaxf(-127.0f, rintf(v.w / sc)));
        qo[c >> 2] = q;
    }
}

// ================= int8 tensor-core GEMM (mma.sync m16n8k32) ====================
#define ASTRIDE 20

__device__ __forceinline__ void mma_s8(int* c, int a0, int a1, int a2, int a3, int b0, int b1)
{
    asm volatile(
        "mma.sync.aligned.m16n8k32.row.col.s32.s8.s8.s32 "
        "{%0,%1,%2,%3}, {%4,%5,%6,%7}, {%8,%9}, {%0,%1,%2,%3};"
        : "+r"(c[0]), "+r"(c[1]), "+r"(c[2]), "+r"(c[3])
        : "r"(a0), "r"(a1), "r"(a2), "r"(a3), "r"(b0), "r"(b1));
}

__global__ __launch_bounds__(256, 2) void gemm_s8_imma_kernel(
    const int8_t* __restrict__ A, const int8_t* __restrict__ Bm,
    const float* __restrict__ sa, const float* __restrict__ sbv,
    const float* __restrict__ bias, float* __restrict__ C, int colsB, int K)
{
    __shared__ int As[2][128 * ASTRIDE];
    __shared__ int Bs[2][128 * ASTRIDE];
    const int tid = threadIdx.x, lane = tid & 31, wid = tid >> 5;
    const int wm = wid & 1, wn = wid >> 1;
    const int g = lane >> 2, tg = lane & 3;
    const int r0 = blockIdx.y * 128, c0 = blockIdx.x * 128;
    const int Kw = K >> 2;
    const int* Ag = (const int*)A;
    const int* Bg = (const int*)Bm;

    int acc[4][4][4] = {};
    const int ldrow = tid >> 2, ldc4 = (tid & 3) * 4;
    const int nt = K / 64;

    {
        uint4 va0 = *(const uint4*)&Ag[(size_t)(r0 + ldrow) * Kw + ldc4];
        uint4 va1 = *(const uint4*)&Ag[(size_t)(r0 + 64 + ldrow) * Kw + ldc4];
        uint4 vb0 = *(const uint4*)&Bg[(size_t)(c0 + ldrow) * Kw + ldc4];
        uint4 vb1 = *(const uint4*)&Bg[(size_t)(c0 + 64 + ldrow) * Kw + ldc4];
        *(uint4*)&As[0][ldrow * ASTRIDE + ldc4] = va0;
        *(uint4*)&As[0][(64 + ldrow) * ASTRIDE + ldc4] = va1;
        *(uint4*)&Bs[0][ldrow * ASTRIDE + ldc4] = vb0;
        *(uint4*)&Bs[0][(64 + ldrow) * ASTRIDE + ldc4] = vb1;
    }
    __syncthreads();

    for (int t = 0; t < nt; t++) {
        const int buf = t & 1;
        const bool more = (t + 1) < nt;
        uint4 va0, va1, vb0, vb1;
        if (more) {
            const int kw = (t + 1) * 16 + ldc4;
            va0 = *(const uint4*)&Ag[(size_t)(r0 + ldrow) * Kw + kw];
            va1 = *(const uint4*)&Ag[(size_t)(r0 + 64 + ldrow) * Kw + kw];
            vb0 = *(const uint4*)&Bg[(size_t)(c0 + ldrow) * Kw + kw];
            vb1 = *(const uint4*)&Bg[(size_t)(c0 + 64 + ldrow) * Kw + kw];
        }
#pragma unroll
        for (int ks = 0; ks < 2; ks++) {
            const int kw = ks * 8;
            int bf[4][2];
#pragma unroll
            for (int n = 0; n < 4; n++) {
                const int col = wn * 32 + n * 8 + g;
                bf[n][0] = Bs[buf][col * ASTRIDE + kw + tg];
                bf[n][1] = Bs[buf][col * ASTRIDE + kw + tg + 4];
            }
#pragma unroll
            for (int m = 0; m < 4; m++) {
                const int row = wm * 64 + m * 16;
                const int a0 = As[buf][(row + g) * ASTRIDE + kw + tg];
                const int a1 = As[buf][(row + 8 + g) * ASTRIDE + kw + tg];
                const int a2 = As[buf][(row + g) * ASTRIDE + kw + tg + 4];
                const int a3 = As[buf][(row + 8 + g) * ASTRIDE + kw + tg + 4];
#pragma unroll
                for (int n = 0; n < 4; n++)
                    mma_s8(acc[m][n], a0, a1, a2, a3, bf[n][0], bf[n][1]);
            }
        }
        __syncthreads();
        if (more) {
            *(uint4*)&As[buf ^ 1][ldrow * ASTRIDE + ldc4] = va0;
            *(uint4*)&As[buf ^ 1][(64 + ldrow) * ASTRIDE + ldc4] = va1;
            *(uint4*)&Bs[buf ^ 1][ldrow * ASTRIDE + ldc4] = vb0;
            *(uint4*)&Bs[buf ^ 1][(64 + ldrow) * ASTRIDE + ldc4] = vb1;
            __syncthreads();
        }
    }

#pragma unroll
    for (int m = 0; m < 4; m++) {
#pragma unroll
        for (int half = 0; half < 2; half++) {
            const int r = r0 + wm * 64 + m * 16 + g + half * 8;
            const float sr = sa[r];
#pragma unroll
            for (int n = 0; n < 4; n++) {
                const int c = c0 + wn * 32 + n * 8 + tg * 2;
                float2 v;
                v.x = (float)acc[m][n][half * 2 + 0] * sr * sbv[c] + bias[c];
                v.y = (float)acc[m][n][half * 2 + 1] * sr * sbv[c + 1] + bias[c + 1];
                *(float2*)&C[(size_t)r * colsB + c] = v;
            }
        }
    }
}

// ================= fp32 GEMM (kv projection) ====================================
__global__ void gemm_f32_kernel(const float* __restrict__ A, const float* __restrict__ Bm,
                                const float* __restrict__ bias, float* __restrict__ C,
                                int colsB, int K)
{
    __shared__ float As[128][17];
    __shared__ float Bs[128][17];
    const int tid = threadIdx.x;
    const int tx = tid & 15, ty = tid >> 4;
    const int r0 = blockIdx.y * 128;
    const int c0 = blockIdx.x * 128;
    float acc[8][8] = {};
    for (int kc = 0; kc < K; kc += 16) {
#pragma unroll
        for (int l = 0; l < 8; l++) {
            int idx = tid + l * 256;
            int r = idx >> 4, c = idx & 15;
            As[r][c] = A[(size_t)(r0 + r) * K + kc + c];
            Bs[r][c] = Bm[(size_t)(c0 + r) * K + kc + c];
        }
        __syncthreads();
#pragma unroll
        for (int kk = 0; kk < 16; kk++) {
            float a[8], b[8];
#pragma unroll
            for (int i = 0; i < 8; i++) a[i] = As[ty * 8 + i][kk];
#pragma unroll
            for (int j = 0; j < 8; j++) b[j] = Bs[tx * 8 + j][kk];
#pragma unroll
            for (int i = 0; i < 8; i++)
#pragma unroll
                for (int j = 0; j < 8; j++)
                    acc[i][j] = fmaf(a[i], b[j], acc[i][j]);
        }
        __syncthreads();
    }
#pragma unroll
    for (int i = 0; i < 8; i++) {
        const int r = r0 + ty * 8 + i;
#pragma unroll
        for (int j = 0; j < 8; j++) {
            const int c = c0 + tx * 8 + j;
            C[(size_t)r * colsB + c] = acc[i][j] + bias[c];
        }
    }
}

// ================= flash attention: 128 q-rows/CTA, online softmax ==============
// grid (N/128, H), 256 threads (16x16, 8x8 per thread). Per-batch pointers.
// smem: SqT[128d][132] | Skv[128][132] (K^T then V) | Ss[128][132] | state[384]
#define AT_S 132
#define ATTN2_FLOATS (3 * 128 * AT_S + 384)

__global__ __launch_bounds__(256, 1) void attn_flash_kernel(
    const float* __restrict__ q, const float* __restrict__ kv, float* __restrict__ o)
{
    extern __shared__ float sm[];
    float* SqT  = sm;                      // Q transposed [d][row]
    float* Skv  = sm + 128 * AT_S;         // K transposed [d][col], then V [m][d]
    float* Ss   = sm + 2 * 128 * AT_S;     // scores / P [row][col]
    float* rowm = sm + 3 * 128 * AT_S;     // running max [128]
    float* rsum = rowm + 128;              // running sum [128]
    float* fsc  = rowm + 256;              // per-tile rescale factor [128]

    const int h = blockIdx.y, n0 = blockIdx.x * 128;
    const int tid = threadIdx.x;
    const int tx = tid & 15, ty = tid >> 4;
    const int warp = tid >> 5, lane = tid & 31;
    const float scale = 0.08838834764831845f;  // 1/sqrt(128)

    // load Q transposed (coalesced read, strided write)
    for (int idx = tid; idx < 128 * DH_; idx += 256) {
        const int r = idx >> 7, d = idx & 127;
        SqT[d * AT_S + r] = q[(size_t)(n0 + r) * D_ + h * DH_ + d];
    }
    if (tid < 128) { rowm[tid] = -1e30f; rsum[tid] = 0.0f; }

    float Oa[8][8] = {};

    for (int t = 0; t < 4; t++) {
        const int m0 = t * 128;
        // ---- K tile transposed: SkT[d][col] ----
        for (int idx = tid; idx < 128 * DH_; idx += 256) {
            const int c = idx >> 7, d = idx & 127;
            Skv[d * AT_S + c] = kv[(size_t)(m0 + c) * (2 * D_) + h * DH_ + d];
        }
        __syncthreads();

        // ---- scores: S = Q K^T (8x8 register tile, vectorized LDS) ----
        {
            float acc[8][8] = {};
#pragma unroll 2
            for (int d = 0; d < DH_; d++) {
                const float4 qa0 = *(const float4*)&SqT[d * AT_S + ty * 8];
                const float4 qa1 = *(const float4*)&SqT[d * AT_S + ty * 8 + 4];
                const float4 kb0 = *(const float4*)&Skv[d * AT_S + tx * 8];
                const float4 kb1 = *(const float4*)&Skv[d * AT_S + tx * 8 + 4];
                const float a[8] = {qa0.x, qa0.y, qa0.z, qa0.w, qa1.x, qa1.y, qa1.z, qa1.w};
                const float b[8] = {kb0.x, kb0.y, kb0.z, kb0.w, kb1.x, kb1.y, kb1.z, kb1.w};
#pragma unroll
                for (int i = 0; i < 8; i++)
#pragma unroll
                    for (int j = 0; j < 8; j++)
                        acc[i][j] = fmaf(a[i], b[j], acc[i][j]);
            }
#pragma unroll
            for (int i = 0; i < 8; i++) {
                float4 s0, s1;
                s0.x = acc[i][0] * scale; s0.y = acc[i][1] * scale;
                s0.z = acc[i][2] * scale; s0.w = acc[i][3] * scale;
                s1.x = acc[i][4] * scale; s1.y = acc[i][5] * scale;
                s1.z = acc[i][6] * scale; s1.w = acc[i][7] * scale;
                *(float4*)&Ss[(ty * 8 + i) * AT_S + tx * 8] = s0;
                *(float4*)&Ss[(ty * 8 + i) * AT_S + tx * 8 + 4] = s1;
            }
        }
        __syncthreads();

        // ---- online softmax over this tile (warp w -> rows 16w..16w+15) ----
        for (int rr = 0; rr < 16; rr++) {
            const int r = warp * 16 + rr;
            float v0 = Ss[r * AT_S + lane];
            float v1 = Ss[r * AT_S + lane + 32];
            float v2 = Ss[r * AT_S + lane + 64];
            float v3 = Ss[r * AT_S + lane + 96];
            float mx = fmaxf(fmaxf(v0, v1), fmaxf(v2, v3));
#pragma unroll
            for (int off = 16; off; off >>= 1) mx = fmaxf(mx, __shfl_xor_sync(0xffffffffu, mx, off));
            const float oldm = rowm[r];
            const float newm = fmaxf(oldm, mx);
            const float e0 = __expf(v0 - newm);
            const float e1 = __expf(v1 - newm);
            const float e2 = __expf(v2 - newm);
            const float e3 = __expf(v3 - newm);
            Ss[r * AT_S + lane]      = e0;
            Ss[r * AT_S + lane + 32] = e1;
            Ss[r * AT_S + lane + 64] = e2;
            Ss[r * AT_S + lane + 96] = e3;
            float sum = e0 + e1 + e2 + e3;
#pragma unroll
            for (int off = 16; off; off >>= 1) sum += __shfl_xor_sync(0xffffffffu, sum, off);
            if (lane == 0) {
                const float f = __expf(oldm - newm);
                fsc[r] = f;
                rsum[r] = rsum[r] * f + sum;
                rowm[r] = newm;
            }
        }
        __syncthreads();

        // ---- V tile row-major: Sv[m][d] (reuses Skv) ----
        for (int idx = tid; idx < 128 * DH_; idx += 256) {
            const int m = idx >> 7, d = idx & 127;
            Skv[m * AT_S + d] = kv[(size_t)(m0 + m) * (2 * D_) + D_ + h * DH_ + d];
        }
        __syncthreads();

        // ---- rescale O and accumulate P @ V ----
        float f[8];
#pragma unroll
        for (int i = 0; i < 8; i++) f[i] = fsc[ty * 8 + i];
#pragma unroll
        for (int i = 0; i < 8; i++)
#pragma unroll
            for (int j = 0; j < 8; j++)
                Oa[i][j] *= f[i];
#pragma unroll 2
        for (int m = 0; m < 128; m++) {
            float pa[8];
#pragma unroll
            for (int i = 0; i < 8; i++) pa[i] = Ss[(ty * 8 + i) * AT_S + m];
            const float4 vb0 = *(const float4*)&Skv[m * AT_S + tx * 8];
            const float4 vb1 = *(const float4*)&Skv[m * AT_S + tx * 8 + 4];
            const float b[8] = {vb0.x, vb0.y, vb0.z, vb0.w, vb1.x, vb1.y, vb1.z, vb1.w};
#pragma unroll
            for (int i = 0; i < 8; i++)
#pragma unroll
                for (int j = 0; j < 8; j++)
                    Oa[i][j] = fmaf(pa[i], b[j], Oa[i][j]);
        }
        __syncthreads();
    }

    // ---- normalize and write out ----
#pragma unroll
    for (int i = 0; i < 8; i++) {
        const float inv = 1.0f / rsum[ty * 8 + i];
        float4 o0, o1;
        o0.x = Oa[i][0] * inv; o0.y = Oa[i][1] * inv;
        o0.z = Oa[i][2] * inv; o0.w = Oa[i][3] * inv;
        o1.x = Oa[i][4] * inv; o1.y = Oa[i][5] * inv;
        o1.z = Oa[i][6] * inv; o1.w = Oa[i][7] * inv;
        float* op = &o[(size_t)(n0 + ty * 8 + i) * D_ + h * DH_ + tx * 8];
        *(float4*)op = o0;
        *(float4*)(op + 4) = o1;
    }
}

// ================= launch: batch-pipelined multi-stream DAG =====================
extern "C" void kernel_launch(void* const* d_in, const int* in_sizes, int n_in,
                              void* d_out, int out_size)
{
    const float* x    = (const float*)d_in[0];
    const float* cond = (const float*)d_in[1];
    const float* wq   = (const float*)d_in[2];
    const float* bq   = (const float*)d_in[3];
    const float* wkv  = (const float*)d_in[4];
    const float* bkv  = (const float*)d_in[5];
    const float* wp   = (const float*)d_in[6];
    const float* bp   = (const float*)d_in[7];
    float* out = (float*)d_out;

    void *p_xq, *p_sx, *p_wqq, *p_swq, *p_wpq, *p_swp, *p_oq, *p_so, *p_q, *p_kv, *p_o;
    cudaGetSymbolAddress(&p_xq, g_xq);   cudaGetSymbolAddress(&p_sx, g_sx);
    cudaGetSymbolAddress(&p_wqq, g_wqq); cudaGetSymbolAddress(&p_swq, g_swq);
    cudaGetSymbolAddress(&p_wpq, g_wpq); cudaGetSymbolAddress(&p_swp, g_swp);
    cudaGetSymbolAddress(&p_oq, g_oq);   cudaGetSymbolAddress(&p_so, g_so);
    cudaGetSymbolAddress(&p_q, g_q);     cudaGetSymbolAddress(&p_kv, g_kv);
    cudaGetSymbolAddress(&p_o, g_o);

    int8_t* xq  = (int8_t*)p_xq;   float* sx  = (float*)p_sx;
    int8_t* wqq = (int8_t*)p_wqq;  float* swq = (float*)p_swq;
    int8_t* wpq = (int8_t*)p_wpq;  float* swp = (float*)p_swp;
    int8_t* oq  = (int8_t*)p_oq;   float* so  = (float*)p_so;
    float* qb   = (float*)p_q;     float* kvb = (float*)p_kv;
    float* ob   = (float*)p_o;

    static cudaStream_t sK = nullptr, sB1 = nullptr;
    static cudaEvent_t eFork, eKV0, eKV1, eQG1, eATTN0, eDONE1;
    if (sK == nullptr) {
        cudaStreamCreateWithFlags(&sK,  cudaStreamNonBlocking);
        cudaStreamCreateWithFlags(&sB1, cudaStreamNonBlocking);
        cudaEventCreateWithFlags(&eFork,  cudaEventDisableTiming);
        cudaEventCreateWithFlags(&eKV0,   cudaEventDisableTiming);
        cudaEventCreateWithFlags(&eKV1,   cudaEventDisableTiming);
        cudaEventCreateWithFlags(&eQG1,   cudaEventDisableTiming);
        cudaEventCreateWithFlags(&eATTN0, cudaEventDisableTiming);
        cudaEventCreateWithFlags(&eDONE1, cudaEventDisableTiming);
    }

    const int attn_smem = ATTN2_FLOATS * sizeof(float);   // ~200 KB
    cudaFuncSetAttribute(attn_flash_kernel, cudaFuncAttributeMaxDynamicSharedMemorySize, attn_smem);

    const size_t XB = (size_t)N_ * D_;
    const size_t KVB = (size_t)M_ * 2 * D_;

    // ---- fork: kv projection (fp32, FMA pipe) on side stream ----
    cudaEventRecord(eFork, 0);
    cudaStreamWaitEvent(sK, eFork, 0);
    {
        dim3 grid((2 * D_) / 128, M_ / 128);
        gemm_f32_kernel<<<grid, 256, 0, sK>>>(cond, wkv, bkv, kvb, 2 * D_, D_);
        cudaEventRecord(eKV0, sK);
        gemm_f32_kernel<<<grid, 256, 0, sK>>>(cond + (size_t)M_ * D_, wkv, bkv,
                                              kvb + KVB, 2 * D_, D_);
        cudaEventRecord(eKV1, sK);
    }

    // ---- main: quantize + q-gemm (tensor pipe) ----
    quant_rows_kernel<<<D_, 256>>>(wq, wqq, swq, D_);
    quant_rows_kernel<<<D_, 256>>>(wp, wpq, swp, D_);
    quant_rows_kernel<<<N_, 256>>>(x, xq, sx, D_);
    {
        dim3 grid(D_ / 128, N_ / 128);
        gemm_s8_imma_kernel<<<grid, 256>>>(xq, wqq, sx, swq, bq, qb, D_, D_);
    }
    quant_rows_kernel<<<N_, 256>>>(x + XB, xq + XB, sx + N_, D_);
    {
        dim3 grid(D_ / 128, N_ / 128);
        gemm_s8_imma_kernel<<<grid, 256>>>(xq + XB, wqq, sx + N_, swq, bq, qb + XB, D_, D_);
    }
    cudaEventRecord(eQG1, 0);

    // ---- attn(b0) on main after kv(b0) ----
    cudaStreamWaitEvent(0, eKV0, 0);
    {
        dim3 grid(N_ / 128, H_);
        attn_flash_kernel<<<grid, 256, attn_smem>>>(qb, kvb, ob);
    }
    cudaEventRecord(eATTN0, 0);

    // ---- branch: attn(b1) + epilogue(b1) ----
    cudaStreamWaitEvent(sB1, eQG1, 0);
    cudaStreamWaitEvent(sB1, eKV1, 0);
    cudaStreamWaitEvent(sB1, eATTN0, 0);
    {
        dim3 grid(N_ / 128, H_);
        attn_flash_kernel<<<grid, 256, attn_smem, sB1>>>(qb + XB, kvb + KVB, ob + XB);
    }
    quant_rows_kernel<<<N_, 256, 0, sB1>>>(ob + XB, oq + XB, so + N_, D_);
    {
        dim3 grid(D_ / 128, N_ / 128);
        gemm_s8_imma_kernel<<<grid, 256, 0, sB1>>>(oq + XB, wpq, so + N_, swp, bp,
                                                   out + XB, D_, D_);
    }
    cudaEventRecord(eDONE1, sB1);

    // ---- main: epilogue(b0) overlaps attn(b1) ----
    quant_rows_kernel<<<N_, 256>>>(ob, oq, so, D_);
    {
        dim3 grid(D_ / 128, N_ / 128);
        gemm_s8_imma_kernel<<<grid, 256>>>(oq, wpq, so, swp, bp, out, D_, D_);
    }

    // ---- join ----
    cudaStreamWaitEvent(0, eDONE1, 0);
}

// round 9
// speedup vs baseline: 1.7397x; 1.1619x over previous
#include <cuda_runtime.h>
#include <cstdint>

#define B_  2
#define N_  4096
#define M_  512
#define D_  2048
#define H_  16
#define DH_ 128

typedef unsigned long long ull;

// ---------------- packed f32x2 helpers (IEEE fp32 per lane, bit-identical) ------
__device__ __forceinline__ ull pack2(float lo, float hi) {
    ull r; asm("mov.b64 %0, {%1, %2};" : "=l"(r) : "f"(lo), "f"(hi)); return r;
}
__device__ __forceinline__ ull bcast2(float v) { return pack2(v, v); }
__device__ __forceinline__ void fma2(ull& d, ull a, ull b) {
    asm("fma.rn.f32x2 %0, %1, %2, %0;" : "+l"(d) : "l"(a), "l"(b));
}
__device__ __forceinline__ ull mul2(ull a, ull b) {
    ull d; asm("mul.rn.f32x2 %0, %1, %2;" : "=l"(d) : "l"(a), "l"(b)); return d;
}
__device__ __forceinline__ ull add2(ull a, ull b) {
    ull d; asm("add.rn.f32x2 %0, %1, %2;" : "=l"(d) : "l"(a), "l"(b)); return d;
}

// ================= scratch ======================================================
__device__ int8_t g_xq[(size_t)B_ * N_ * D_];
__device__ float  g_sx[B_ * N_];
__device__ int8_t g_wqq[(size_t)D_ * D_];
__device__ float  g_swq[D_];
__device__ int8_t g_wpq[(size_t)D_ * D_];
__device__ float  g_swp[D_];
__device__ int8_t g_oq[(size_t)B_ * N_ * D_];
__device__ float  g_so[B_ * N_];
__device__ float  g_q[(size_t)B_ * N_ * D_];
__device__ float  g_kv[(size_t)B_ * M_ * 2 * D_];
__device__ float  g_o[(size_t)B_ * N_ * D_];

// ================= per-row int8 fake-quant (matches jax _qdq exactly) ===========
__global__ void quant_rows_kernel(const float* __restrict__ in, int8_t* __restrict__ outq,
                                  float* __restrict__ scales, int cols)
{
    const int row = blockIdx.x;
    const float* p = in + (size_t)row * cols;
    __shared__ float red[256];
    float mx = 0.0f;
    for (int c = threadIdx.x * 4; c < cols; c += blockDim.x * 4) {
        float4 v = *(const float4*)&p[c];
        mx = fmaxf(mx, fmaxf(fmaxf(fabsf(v.x), fabsf(v.y)), fmaxf(fabsf(v.z), fabsf(v.w))));
    }
    red[threadIdx.x] = mx;
    __syncthreads();
    for (int s = 128; s > 0; s >>= 1) {
        if (threadIdx.x < s)
            red[threadIdx.x] = fmaxf(red[threadIdx.x], red[threadIdx.x + s]);
        __syncthreads();
    }
    const float sc = fmaxf(red[0] / 127.0f, 1e-8f);
    if (threadIdx.x == 0) scales[row] = sc;
    char4* qo = (char4*)(outq + (size_t)row * cols);
    for (int c = threadIdx.x * 4; c < cols; c += blockDim.x * 4) {
        float4 v = *(const float4*)&p[c];
        char4 q;
        q.x = (int8_t)fminf(127.0f, fmaxf(-127.0f, rintf(v.x / sc)));
        q.y = (int8_t)fminf(127.0f, fmaxf(-127.0f, rintf(v.y / sc)));
        q.z = (int8_t)fminf(127.0f, fmaxf(-127.0f, rintf(v.z / sc)));
        q.w = (int8_t)fminf(127.0f, fmaxf(-127.0f, rintf(v.w / sc)));
        qo[c >> 2] = q;
    }
}

// ================= int8 tensor-core GEMM (mma.sync m16n8k32) ====================
#define ASTRIDE 20

__device__ __forceinline__ void mma_s8(int* c, int a0, int a1, int a2, int a3, int b0, int b1)
{
    asm volatile(
        "mma.sync.aligned.m16n8k32.row.col.s32.s8.s8.s32 "
        "{%0,%1,%2,%3}, {%4,%5,%6,%7}, {%8,%9}, {%0,%1,%2,%3};"
        : "+r"(c[0]), "+r"(c[1]), "+r"(c[2]), "+r"(c[3])
        : "r"(a0), "r"(a1), "r"(a2), "r"(a3), "r"(b0), "r"(b1));
}

__global__ __launch_bounds__(256, 2) void gemm_s8_imma_kernel(
    const int8_t* __restrict__ A, const int8_t* __restrict__ Bm,
    const float* __restrict__ sa, const float* __restrict__ sbv,
    const float* __restrict__ bias, float* __restrict__ C, int colsB, int K)
{
    __shared__ int As[2][128 * ASTRIDE];
    __shared__ int Bs[2][128 * ASTRIDE];
    const int tid = threadIdx.x, lane = tid & 31, wid = tid >> 5;
    const int wm = wid & 1, wn = wid >> 1;
    const int g = lane >> 2, tg = lane & 3;
    const int r0 = blockIdx.y * 128, c0 = blockIdx.x * 128;
    const int Kw = K >> 2;
    const int* Ag = (const int*)A;
    const int* Bg = (const int*)Bm;

    int acc[4][4][4] = {};
    const int ldrow = tid >> 2, ldc4 = (tid & 3) * 4;
    const int nt = K / 64;

    {
        uint4 va0 = *(const uint4*)&Ag[(size_t)(r0 + ldrow) * Kw + ldc4];
        uint4 va1 = *(const uint4*)&Ag[(size_t)(r0 + 64 + ldrow) * Kw + ldc4];
        uint4 vb0 = *(const uint4*)&Bg[(size_t)(c0 + ldrow) * Kw + ldc4];
        uint4 vb1 = *(const uint4*)&Bg[(size_t)(c0 + 64 + ldrow) * Kw + ldc4];
        *(uint4*)&As[0][ldrow * ASTRIDE + ldc4] = va0;
        *(uint4*)&As[0][(64 + ldrow) * ASTRIDE + ldc4] = va1;
        *(uint4*)&Bs[0][ldrow * ASTRIDE + ldc4] = vb0;
        *(uint4*)&Bs[0][(64 + ldrow) * ASTRIDE + ldc4] = vb1;
    }
    __syncthreads();

    for (int t = 0; t < nt; t++) {
        const int buf = t & 1;
        const bool more = (t + 1) < nt;
        uint4 va0, va1, vb0, vb1;
        if (more) {
            const int kw = (t + 1) * 16 + ldc4;
            va0 = *(const uint4*)&Ag[(size_t)(r0 + ldrow) * Kw + kw];
            va1 = *(const uint4*)&Ag[(size_t)(r0 + 64 + ldrow) * Kw + kw];
            vb0 = *(const uint4*)&Bg[(size_t)(c0 + ldrow) * Kw + kw];
            vb1 = *(const uint4*)&Bg[(size_t)(c0 + 64 + ldrow) * Kw + kw];
        }
#pragma unroll
        for (int ks = 0; ks < 2; ks++) {
            const int kw = ks * 8;
            int bf[4][2];
#pragma unroll
            for (int n = 0; n < 4; n++) {
                const int col = wn * 32 + n * 8 + g;
                bf[n][0] = Bs[buf][col * ASTRIDE + kw + tg];
                bf[n][1] = Bs[buf][col * ASTRIDE + kw + tg + 4];
            }
#pragma unroll
            for (int m = 0; m < 4; m++) {
                const int row = wm * 64 + m * 16;
                const int a0 = As[buf][(row + g) * ASTRIDE + kw + tg];
                const int a1 = As[buf][(row + 8 + g) * ASTRIDE + kw + tg];
                const int a2 = As[buf][(row + g) * ASTRIDE + kw + tg + 4];
                const int a3 = As[buf][(row + 8 + g) * ASTRIDE + kw + tg + 4];
#pragma unroll
                for (int n = 0; n < 4; n++)
                    mma_s8(acc[m][n], a0, a1, a2, a3, bf[n][0], bf[n][1]);
            }
        }
        __syncthreads();
        if (more) {
            *(uint4*)&As[buf ^ 1][ldrow * ASTRIDE + ldc4] = va0;
            *(uint4*)&As[buf ^ 1][(64 + ldrow) * ASTRIDE + ldc4] = va1;
            *(uint4*)&Bs[buf ^ 1][ldrow * ASTRIDE + ldc4] = vb0;
            *(uint4*)&Bs[buf ^ 1][(64 + ldrow) * ASTRIDE + ldc4] = vb1;
            __syncthreads();
        }
    }

#pragma unroll
    for (int m = 0; m < 4; m++) {
#pragma unroll
        for (int half = 0; half < 2; half++) {
            const int r = r0 + wm * 64 + m * 16 + g + half * 8;
            const float sr = sa[r];
#pragma unroll
            for (int n = 0; n < 4; n++) {
                const int c = c0 + wn * 32 + n * 8 + tg * 2;
                float2 v;
                v.x = (float)acc[m][n][half * 2 + 0] * sr * sbv[c] + bias[c];
                v.y = (float)acc[m][n][half * 2 + 1] * sr * sbv[c + 1] + bias[c + 1];
                *(float2*)&C[(size_t)r * colsB + c] = v;
            }
        }
    }
}

// ================= fp32 GEMM (kv projection) — packed FFMA2 =====================
__global__ void gemm_f32_kernel(const float* __restrict__ A, const float* __restrict__ Bm,
                                const float* __restrict__ bias, float* __restrict__ C,
                                int colsB, int K)
{
    __shared__ float As[128][17];
    __shared__ float BsT[16][132];   // transposed: [k][col], pairs contiguous along col
    const int tid = threadIdx.x;
    const int tx = tid & 15, ty = tid >> 4;
    const int r0 = blockIdx.y * 128;
    const int c0 = blockIdx.x * 128;
    ull acc2[8][4] = {};
    for (int kc = 0; kc < K; kc += 16) {
#pragma unroll
        for (int l = 0; l < 8; l++) {
            int idx = tid + l * 256;
            int r = idx >> 4, c = idx & 15;
            As[r][c] = A[(size_t)(r0 + r) * K + kc + c];
            BsT[c][r] = Bm[(size_t)(c0 + r) * K + kc + c];
        }
        __syncthreads();
#pragma unroll
        for (int kk = 0; kk < 16; kk++) {
            const ulonglong2 bl0 = *(const ulonglong2*)&BsT[kk][tx * 8];
            const ulonglong2 bl1 = *(const ulonglong2*)&BsT[kk][tx * 8 + 4];
            const ull b2[4] = {bl0.x, bl0.y, bl1.x, bl1.y};
            ull a2[8];
#pragma unroll
            for (int i = 0; i < 8; i++) a2[i] = bcast2(As[ty * 8 + i][kk]);
#pragma unroll
            for (int i = 0; i < 8; i++)
#pragma unroll
                for (int j = 0; j < 4; j++)
                    fma2(acc2[i][j], a2[i], b2[j]);
        }
        __syncthreads();
    }
    const ull bias2[4] = {
        *(const ull*)&bias[c0 + tx * 8],     *(const ull*)&bias[c0 + tx * 8 + 2],
        *(const ull*)&bias[c0 + tx * 8 + 4], *(const ull*)&bias[c0 + tx * 8 + 6]};
#pragma unroll
    for (int i = 0; i < 8; i++) {
        const int r = r0 + ty * 8 + i;
        ull* cp = (ull*)&C[(size_t)r * colsB + c0 + tx * 8];
#pragma unroll
        for (int j = 0; j < 4; j++)
            cp[j] = add2(acc2[i][j], bias2[j]);
    }
}

// ================= flash attention — packed FFMA2 ===============================
// grid (N/128, H), 256 threads (16x16, 8x8 per thread). Per-batch pointers.
#define AT_S 132
#define ATTN2_FLOATS (3 * 128 * AT_S + 384)

__global__ __launch_bounds__(256, 1) void attn_flash_kernel(
    const float* __restrict__ q, const float* __restrict__ kv, float* __restrict__ o)
{
    extern __shared__ float sm[];
    float* SqT  = sm;                      // Q transposed [d][row]
    float* Skv  = sm + 128 * AT_S;         // K transposed [d][col], then V [m][d]
    float* Ss   = sm + 2 * 128 * AT_S;     // scores / P [row][col]
    float* rowm = sm + 3 * 128 * AT_S;
    float* rsum = rowm + 128;
    float* fsc  = rowm + 256;

    const int h = blockIdx.y, n0 = blockIdx.x * 128;
    const int tid = threadIdx.x;
    const int tx = tid & 15, ty = tid >> 4;
    const int warp = tid >> 5, lane = tid & 31;
    const float scale = 0.08838834764831845f;  // 1/sqrt(128)

    for (int idx = tid; idx < 128 * DH_; idx += 256) {
        const int r = idx >> 7, d = idx & 127;
        SqT[d * AT_S + r] = q[(size_t)(n0 + r) * D_ + h * DH_ + d];
    }
    if (tid < 128) { rowm[tid] = -1e30f; rsum[tid] = 0.0f; }

    ull Oa2[8][4] = {};

    for (int t = 0; t < 4; t++) {
        const int m0 = t * 128;
        // ---- K tile transposed: [d][col] ----
        for (int idx = tid; idx < 128 * DH_; idx += 256) {
            const int c = idx >> 7, d = idx & 127;
            Skv[d * AT_S + c] = kv[(size_t)(m0 + c) * (2 * D_) + h * DH_ + d];
        }
        __syncthreads();

        // ---- scores: S = Q K^T (packed j-pairs) ----
        {
            ull acc2[8][4] = {};
#pragma unroll 2
            for (int d = 0; d < DH_; d++) {
                const float4 qa0 = *(const float4*)&SqT[d * AT_S + ty * 8];
                const float4 qa1 = *(const float4*)&SqT[d * AT_S + ty * 8 + 4];
                const ulonglong2 kb0 = *(const ulonglong2*)&Skv[d * AT_S + tx * 8];
                const ulonglong2 kb1 = *(const ulonglong2*)&Skv[d * AT_S + tx * 8 + 4];
                const ull b2[4] = {kb0.x, kb0.y, kb1.x, kb1.y};
                const ull a2[8] = {bcast2(qa0.x), bcast2(qa0.y), bcast2(qa0.z), bcast2(qa0.w),
                                   bcast2(qa1.x), bcast2(qa1.y), bcast2(qa1.z), bcast2(qa1.w)};
#pragma unroll
                for (int i = 0; i < 8; i++)
#pragma unroll
                    for (int j = 0; j < 4; j++)
                        fma2(acc2[i][j], a2[i], b2[j]);
            }
            const ull sc2 = bcast2(scale);
#pragma unroll
            for (int i = 0; i < 8; i++) {
                ull* sp = (ull*)&Ss[(ty * 8 + i) * AT_S + tx * 8];
#pragma unroll
                for (int j = 0; j < 4; j++)
                    sp[j] = mul2(acc2[i][j], sc2);
            }
        }
        __syncthreads();

        // ---- online softmax over this tile ----
        for (int rr = 0; rr < 16; rr++) {
            const int r = warp * 16 + rr;
            float v0 = Ss[r * AT_S + lane];
            float v1 = Ss[r * AT_S + lane + 32];
            float v2 = Ss[r * AT_S + lane + 64];
            float v3 = Ss[r * AT_S + lane + 96];
            float mx = fmaxf(fmaxf(v0, v1), fmaxf(v2, v3));
#pragma unroll
            for (int off = 16; off; off >>= 1) mx = fmaxf(mx, __shfl_xor_sync(0xffffffffu, mx, off));
            const float oldm = rowm[r];
            const float newm = fmaxf(oldm, mx);
            const float e0 = __expf(v0 - newm);
            const float e1 = __expf(v1 - newm);
            const float e2 = __expf(v2 - newm);
            const float e3 = __expf(v3 - newm);
            Ss[r * AT_S + lane]      = e0;
            Ss[r * AT_S + lane + 32] = e1;
            Ss[r * AT_S + lane + 64] = e2;
            Ss[r * AT_S + lane + 96] = e3;
            float sum = e0 + e1 + e2 + e3;
#pragma unroll
            for (int off = 16; off; off >>= 1) sum += __shfl_xor_sync(0xffffffffu, sum, off);
            if (lane == 0) {
                const float f = __expf(oldm - newm);
                fsc[r] = f;
                rsum[r] = rsum[r] * f + sum;
                rowm[r] = newm;
            }
        }
        __syncthreads();

        // ---- V tile row-major [m][d] ----
        for (int idx = tid; idx < 128 * DH_; idx += 256) {
            const int m = idx >> 7, d = idx & 127;
            Skv[m * AT_S + d] = kv[(size_t)(m0 + m) * (2 * D_) + D_ + h * DH_ + d];
        }
        __syncthreads();

        // ---- rescale O and accumulate P @ V (packed) ----
#pragma unroll
        for (int i = 0; i < 8; i++) {
            const ull f2 = bcast2(fsc[ty * 8 + i]);
#pragma unroll
            for (int j = 0; j < 4; j++)
                Oa2[i][j] = mul2(Oa2[i][j], f2);
        }
#pragma unroll 2
        for (int m = 0; m < 128; m++) {
            ull a2[8];
#pragma unroll
            for (int i = 0; i < 8; i++) a2[i] = bcast2(Ss[(ty * 8 + i) * AT_S + m]);
            const ulonglong2 vb0 = *(const ulonglong2*)&Skv[m * AT_S + tx * 8];
            const ulonglong2 vb1 = *(const ulonglong2*)&Skv[m * AT_S + tx * 8 + 4];
            const ull b2[4] = {vb0.x, vb0.y, vb1.x, vb1.y};
#pragma unroll
            for (int i = 0; i < 8; i++)
#pragma unroll
                for (int j = 0; j < 4; j++)
                    fma2(Oa2[i][j], a2[i], b2[j]);
        }
        __syncthreads();
    }

    // ---- normalize and write out (packed) ----
#pragma unroll
    for (int i = 0; i < 8; i++) {
        const ull inv2 = bcast2(1.0f / rsum[ty * 8 + i]);
        ull* op = (ull*)&o[(size_t)(n0 + ty * 8 + i) * D_ + h * DH_ + tx * 8];
#pragma unroll
        for (int j = 0; j < 4; j++)
            op[j] = mul2(Oa2[i][j], inv2);
    }
}

// ================= launch: batch-pipelined multi-stream DAG =====================
extern "C" void kernel_launch(void* const* d_in, const int* in_sizes, int n_in,
                              void* d_out, int out_size)
{
    const float* x    = (const float*)d_in[0];
    const float* cond = (const float*)d_in[1];
    const float* wq   = (const float*)d_in[2];
    const float* bq   = (const float*)d_in[3];
    const float* wkv  = (const float*)d_in[4];
    const float* bkv  = (const float*)d_in[5];
    const float* wp   = (const float*)d_in[6];
    const float* bp   = (const float*)d_in[7];
    float* out = (float*)d_out;

    void *p_xq, *p_sx, *p_wqq, *p_swq, *p_wpq, *p_swp, *p_oq, *p_so, *p_q, *p_kv, *p_o;
    cudaGetSymbolAddress(&p_xq, g_xq);   cudaGetSymbolAddress(&p_sx, g_sx);
    cudaGetSymbolAddress(&p_wqq, g_wqq); cudaGetSymbolAddress(&p_swq, g_swq);
    cudaGetSymbolAddress(&p_wpq, g_wpq); cudaGetSymbolAddress(&p_swp, g_swp);
    cudaGetSymbolAddress(&p_oq, g_oq);   cudaGetSymbolAddress(&p_so, g_so);
    cudaGetSymbolAddress(&p_q, g_q);     cudaGetSymbolAddress(&p_kv, g_kv);
    cudaGetSymbolAddress(&p_o, g_o);

    int8_t* xq  = (int8_t*)p_xq;   float* sx  = (float*)p_sx;
    int8_t* wqq = (int8_t*)p_wqq;  float* swq = (float*)p_swq;
    int8_t* wpq = (int8_t*)p_wpq;  float* swp = (float*)p_swp;
    int8_t* oq  = (int8_t*)p_oq;   float* so  = (float*)p_so;
    float* qb   = (float*)p_q;     float* kvb = (float*)p_kv;
    float* ob   = (float*)p_o;

    static cudaStream_t sK = nullptr, sB1 = nullptr;
    static cudaEvent_t eFork, eKV0, eKV1, eQG1, eDONE1;
    if (sK == nullptr) {
        cudaStreamCreateWithFlags(&sK,  cudaStreamNonBlocking);
        cudaStreamCreateWithFlags(&sB1, cudaStreamNonBlocking);
        cudaEventCreateWithFlags(&eFork,  cudaEventDisableTiming);
        cudaEventCreateWithFlags(&eKV0,   cudaEventDisableTiming);
        cudaEventCreateWithFlags(&eKV1,   cudaEventDisableTiming);
        cudaEventCreateWithFlags(&eQG1,   cudaEventDisableTiming);
        cudaEventCreateWithFlags(&eDONE1, cudaEventDisableTiming);
    }

    const int attn_smem = ATTN2_FLOATS * sizeof(float);   // ~200 KB
    cudaFuncSetAttribute(attn_flash_kernel, cudaFuncAttributeMaxDynamicSharedMemorySize, attn_smem);

    const size_t XB = (size_t)N_ * D_;
    const size_t KVB = (size_t)M_ * 2 * D_;

    // ---- fork: kv projection (fp32 FFMA2) on side stream ----
    cudaEventRecord(eFork, 0);
    cudaStreamWaitEvent(sK, eFork, 0);
    {
        dim3 grid((2 * D_) / 128, M_ / 128);
        gemm_f32_kernel<<<grid, 256, 0, sK>>>(cond, wkv, bkv, kvb, 2 * D_, D_);
        cudaEventRecord(eKV0, sK);
        gemm_f32_kernel<<<grid, 256, 0, sK>>>(cond + (size_t)M_ * D_, wkv, bkv,
                                              kvb + KVB, 2 * D_, D_);
        cudaEventRecord(eKV1, sK);
    }

    // ---- main: quantize + q-gemm (tensor pipe) ----
    quant_rows_kernel<<<D_, 256>>>(wq, wqq, swq, D_);
    quant_rows_kernel<<<D_, 256>>>(wp, wpq, swp, D_);
    quant_rows_kernel<<<N_, 256>>>(x, xq, sx, D_);
    {
        dim3 grid(D_ / 128, N_ / 128);
        gemm_s8_imma_kernel<<<grid, 256>>>(xq, wqq, sx, swq, bq, qb, D_, D_);
    }
    quant_rows_kernel<<<N_, 256>>>(x + XB, xq + XB, sx + N_, D_);
    {
        dim3 grid(D_ / 128, N_ / 128);
        gemm_s8_imma_kernel<<<grid, 256>>>(xq + XB, wqq, sx + N_, swq, bq, qb + XB, D_, D_);
    }
    cudaEventRecord(eQG1, 0);

    // ---- attn(b0) on main after kv(b0) ----
    cudaStreamWaitEvent(0, eKV0, 0);
    {
        dim3 grid(N_ / 128, H_);
        attn_flash_kernel<<<grid, 256, attn_smem>>>(qb, kvb, ob);
    }

    // ---- attn(b1) + epilogue(b1) on sB1 (no serialization vs attn0) ----
    cudaStreamWaitEvent(sB1, eQG1, 0);
    cudaStreamWaitEvent(sB1, eKV1, 0);
    {
        dim3 grid(N_ / 128, H_);
        attn_flash_kernel<<<grid, 256, attn_smem, sB1>>>(qb + XB, kvb + KVB, ob + XB);
    }
    quant_rows_kernel<<<N_, 256, 0, sB1>>>(ob + XB, oq + XB, so + N_, D_);
    {
        dim3 grid(D_ / 128, N_ / 128);
        gemm_s8_imma_kernel<<<grid, 256, 0, sB1>>>(oq + XB, wpq, so + N_, swp, bp,
                                                   out + XB, D_, D_);
    }
    cudaEventRecord(eDONE1, sB1);

    // ---- main: epilogue(b0) ----
    quant_rows_kernel<<<N_, 256>>>(ob, oq, so, D_);
    {
        dim3 grid(D_ / 128, N_ / 128);
        gemm_s8_imma_kernel<<<grid, 256>>>(oq, wpq, so, swp, bp, out, D_, D_);
    }

    // ---- join ----
    cudaStreamWaitEvent(0, eDONE1, 0);
}

// round 10
// speedup vs baseline: 1.9300x; 1.1094x over previous
#include <cuda_runtime.h>
#include <cstdint>

#define B_  2
#define N_  4096
#define M_  512
#define D_  2048
#define H_  16
#define DH_ 128

typedef unsigned long long ull;

// ---------------- packed f32x2 helpers (IEEE fp32 per lane, bit-identical) ------
__device__ __forceinline__ ull pack2(float lo, float hi) {
    ull r; asm("mov.b64 %0, {%1, %2};" : "=l"(r) : "f"(lo), "f"(hi)); return r;
}
__device__ __forceinline__ ull bcast2(float v) { return pack2(v, v); }
__device__ __forceinline__ void fma2(ull& d, ull a, ull b) {
    asm("fma.rn.f32x2 %0, %1, %2, %0;" : "+l"(d) : "l"(a), "l"(b));
}
__device__ __forceinline__ ull mul2(ull a, ull b) {
    ull d; asm("mul.rn.f32x2 %0, %1, %2;" : "=l"(d) : "l"(a), "l"(b)); return d;
}
__device__ __forceinline__ ull add2(ull a, ull b) {
    ull d; asm("add.rn.f32x2 %0, %1, %2;" : "=l"(d) : "l"(a), "l"(b)); return d;
}

// ================= scratch ======================================================
__device__ int8_t g_xq[(size_t)B_ * N_ * D_];
__device__ float  g_sx[B_ * N_];
__device__ int8_t g_wqq[(size_t)D_ * D_];
__device__ float  g_swq[D_];
__device__ int8_t g_wpq[(size_t)D_ * D_];
__device__ float  g_swp[D_];
__device__ int8_t g_oq[(size_t)B_ * N_ * D_];
__device__ float  g_so[B_ * N_];
__device__ float  g_q[(size_t)B_ * N_ * D_];
__device__ float  g_kv[(size_t)B_ * M_ * 2 * D_];
__device__ float  g_o[(size_t)B_ * N_ * D_];

// ================= per-row int8 fake-quant (matches jax _qdq exactly) ===========
__global__ void quant_rows_kernel(const float* __restrict__ in, int8_t* __restrict__ outq,
                                  float* __restrict__ scales, int cols)
{
    const int row = blockIdx.x;
    const float* p = in + (size_t)row * cols;
    __shared__ float red[256];
    float mx = 0.0f;
    for (int c = threadIdx.x * 4; c < cols; c += blockDim.x * 4) {
        float4 v = *(const float4*)&p[c];
        mx = fmaxf(mx, fmaxf(fmaxf(fabsf(v.x), fabsf(v.y)), fmaxf(fabsf(v.z), fabsf(v.w))));
    }
    red[threadIdx.x] = mx;
    __syncthreads();
    for (int s = 128; s > 0; s >>= 1) {
        if (threadIdx.x < s)
            red[threadIdx.x] = fmaxf(red[threadIdx.x], red[threadIdx.x + s]);
        __syncthreads();
    }
    const float sc = fmaxf(red[0] / 127.0f, 1e-8f);
    if (threadIdx.x == 0) scales[row] = sc;
    char4* qo = (char4*)(outq + (size_t)row * cols);
    for (int c = threadIdx.x * 4; c < cols; c += blockDim.x * 4) {
        float4 v = *(const float4*)&p[c];
        char4 q;
        q.x = (int8_t)fminf(127.0f, fmaxf(-127.0f, rintf(v.x / sc)));
        q.y = (int8_t)fminf(127.0f, fmaxf(-127.0f, rintf(v.y / sc)));
        q.z = (int8_t)fminf(127.0f, fmaxf(-127.0f, rintf(v.z / sc)));
        q.w = (int8_t)fminf(127.0f, fmaxf(-127.0f, rintf(v.w / sc)));
        qo[c >> 2] = q;
    }
}

// ================= int8 tensor-core GEMM (mma.sync m16n8k32) ====================
#define ASTRIDE 20

__device__ __forceinline__ void mma_s8(int* c, int a0, int a1, int a2, int a3, int b0, int b1)
{
    asm volatile(
        "mma.sync.aligned.m16n8k32.row.col.s32.s8.s8.s32 "
        "{%0,%1,%2,%3}, {%4,%5,%6,%7}, {%8,%9}, {%0,%1,%2,%3};"
        : "+r"(c[0]), "+r"(c[1]), "+r"(c[2]), "+r"(c[3])
        : "r"(a0), "r"(a1), "r"(a2), "r"(a3), "r"(b0), "r"(b1));
}

__global__ __launch_bounds__(256, 2) void gemm_s8_imma_kernel(
    const int8_t* __restrict__ A, const int8_t* __restrict__ Bm,
    const float* __restrict__ sa, const float* __restrict__ sbv,
    const float* __restrict__ bias, float* __restrict__ C, int colsB, int K)
{
    __shared__ int As[2][128 * ASTRIDE];
    __shared__ int Bs[2][128 * ASTRIDE];
    const int tid = threadIdx.x, lane = tid & 31, wid = tid >> 5;
    const int wm = wid & 1, wn = wid >> 1;
    const int g = lane >> 2, tg = lane & 3;
    const int r0 = blockIdx.y * 128, c0 = blockIdx.x * 128;
    const int Kw = K >> 2;
    const int* Ag = (const int*)A;
    const int* Bg = (const int*)Bm;

    int acc[4][4][4] = {};
    const int ldrow = tid >> 2, ldc4 = (tid & 3) * 4;
    const int nt = K / 64;

    {
        uint4 va0 = *(const uint4*)&Ag[(size_t)(r0 + ldrow) * Kw + ldc4];
        uint4 va1 = *(const uint4*)&Ag[(size_t)(r0 + 64 + ldrow) * Kw + ldc4];
        uint4 vb0 = *(const uint4*)&Bg[(size_t)(c0 + ldrow) * Kw + ldc4];
        uint4 vb1 = *(const uint4*)&Bg[(size_t)(c0 + 64 + ldrow) * Kw + ldc4];
        *(uint4*)&As[0][ldrow * ASTRIDE + ldc4] = va0;
        *(uint4*)&As[0][(64 + ldrow) * ASTRIDE + ldc4] = va1;
        *(uint4*)&Bs[0][ldrow * ASTRIDE + ldc4] = vb0;
        *(uint4*)&Bs[0][(64 + ldrow) * ASTRIDE + ldc4] = vb1;
    }
    __syncthreads();

    for (int t = 0; t < nt; t++) {
        const int buf = t & 1;
        const bool more = (t + 1) < nt;
        uint4 va0, va1, vb0, vb1;
        if (more) {
            const int kw = (t + 1) * 16 + ldc4;
            va0 = *(const uint4*)&Ag[(size_t)(r0 + ldrow) * Kw + kw];
            va1 = *(const uint4*)&Ag[(size_t)(r0 + 64 + ldrow) * Kw + kw];
            vb0 = *(const uint4*)&Bg[(size_t)(c0 + ldrow) * Kw + kw];
            vb1 = *(const uint4*)&Bg[(size_t)(c0 + 64 + ldrow) * Kw + kw];
        }
#pragma unroll
        for (int ks = 0; ks < 2; ks++) {
            const int kw = ks * 8;
            int bf[4][2];
#pragma unroll
            for (int n = 0; n < 4; n++) {
                const int col = wn * 32 + n * 8 + g;
                bf[n][0] = Bs[buf][col * ASTRIDE + kw + tg];
                bf[n][1] = Bs[buf][col * ASTRIDE + kw + tg + 4];
            }
#pragma unroll
            for (int m = 0; m < 4; m++) {
                const int row = wm * 64 + m * 16;
                const int a0 = As[buf][(row + g) * ASTRIDE + kw + tg];
                const int a1 = As[buf][(row + 8 + g) * ASTRIDE + kw + tg];
                const int a2 = As[buf][(row + g) * ASTRIDE + kw + tg + 4];
                const int a3 = As[buf][(row + 8 + g) * ASTRIDE + kw + tg + 4];
#pragma unroll
                for (int n = 0; n < 4; n++)
                    mma_s8(acc[m][n], a0, a1, a2, a3, bf[n][0], bf[n][1]);
            }
        }
        __syncthreads();
        if (more) {
            *(uint4*)&As[buf ^ 1][ldrow * ASTRIDE + ldc4] = va0;
            *(uint4*)&As[buf ^ 1][(64 + ldrow) * ASTRIDE + ldc4] = va1;
            *(uint4*)&Bs[buf ^ 1][ldrow * ASTRIDE + ldc4] = vb0;
            *(uint4*)&Bs[buf ^ 1][(64 + ldrow) * ASTRIDE + ldc4] = vb1;
            __syncthreads();
        }
    }

#pragma unroll
    for (int m = 0; m < 4; m++) {
#pragma unroll
        for (int half = 0; half < 2; half++) {
            const int r = r0 + wm * 64 + m * 16 + g + half * 8;
            const float sr = sa[r];
#pragma unroll
            for (int n = 0; n < 4; n++) {
                const int c = c0 + wn * 32 + n * 8 + tg * 2;
                float2 v;
                v.x = (float)acc[m][n][half * 2 + 0] * sr * sbv[c] + bias[c];
                v.y = (float)acc[m][n][half * 2 + 1] * sr * sbv[c + 1] + bias[c + 1];
                *(float2*)&C[(size_t)r * colsB + c] = v;
            }
        }
    }
}

// ================= fp32 GEMM (kv projection) — packed FFMA2 =====================
__global__ void gemm_f32_kernel(const float* __restrict__ A, const float* __restrict__ Bm,
                                const float* __restrict__ bias, float* __restrict__ C,
                                int colsB, int K)
{
    __shared__ float As[128][17];
    __shared__ float BsT[16][132];
    const int tid = threadIdx.x;
    const int tx = tid & 15, ty = tid >> 4;
    const int r0 = blockIdx.y * 128;
    const int c0 = blockIdx.x * 128;
    ull acc2[8][4] = {};
    for (int kc = 0; kc < K; kc += 16) {
#pragma unroll
        for (int l = 0; l < 8; l++) {
            int idx = tid + l * 256;
            int r = idx >> 4, c = idx & 15;
            As[r][c] = A[(size_t)(r0 + r) * K + kc + c];
            BsT[c][r] = Bm[(size_t)(c0 + r) * K + kc + c];
        }
        __syncthreads();
#pragma unroll
        for (int kk = 0; kk < 16; kk++) {
            const ulonglong2 bl0 = *(const ulonglong2*)&BsT[kk][tx * 8];
            const ulonglong2 bl1 = *(const ulonglong2*)&BsT[kk][tx * 8 + 4];
            const ull b2[4] = {bl0.x, bl0.y, bl1.x, bl1.y};
            ull a2[8];
#pragma unroll
            for (int i = 0; i < 8; i++) a2[i] = bcast2(As[ty * 8 + i][kk]);
#pragma unroll
            for (int i = 0; i < 8; i++)
#pragma unroll
                for (int j = 0; j < 4; j++)
                    fma2(acc2[i][j], a2[i], b2[j]);
        }
        __syncthreads();
    }
    const ull bias2[4] = {
        *(const ull*)&bias[c0 + tx * 8],     *(const ull*)&bias[c0 + tx * 8 + 2],
        *(const ull*)&bias[c0 + tx * 8 + 4], *(const ull*)&bias[c0 + tx * 8 + 6]};
#pragma unroll
    for (int i = 0; i < 8; i++) {
        const int r = r0 + ty * 8 + i;
        ull* cp = (ull*)&C[(size_t)r * colsB + c0 + tx * 8];
#pragma unroll
        for (int j = 0; j < 4; j++)
            cp[j] = add2(acc2[i][j], bias2[j]);
    }
}

// ================= flash attention — FFMA2 + vectorized loads ===================
// grid (N/128, H), 256 threads (16x16, 8x8 per thread). Per-batch pointers.
#define AT_S 132
#define ATTN2_FLOATS (3 * 128 * AT_S + 384)

__global__ __launch_bounds__(256, 1) void attn_flash_kernel(
    const float* __restrict__ q, const float* __restrict__ kv, float* __restrict__ o)
{
    extern __shared__ float sm[];
    float* SqT  = sm;                      // Q transposed [d][row]
    float* Skv  = sm + 128 * AT_S;         // K transposed [d][col], then V [m][d]
    float* Ss   = sm + 2 * 128 * AT_S;     // scratch / scores / P [row][col]
    float* rowm = sm + 3 * 128 * AT_S;
    float* rsum = rowm + 128;
    float* fsc  = rowm + 256;

    const int h = blockIdx.y, n0 = blockIdx.x * 128;
    const int tid = threadIdx.x;
    const int tx = tid & 15, ty = tid >> 4;
    const int warp = tid >> 5, lane = tid & 31;
    const float scale = 0.08838834764831845f;  // 1/sqrt(128)

    // ---- Q load: stage 1 row-major into Ss scratch (vectorized) ----
    for (int idx = tid; idx < 128 * 32; idx += 256) {
        const int r = idx >> 5, dq = (idx & 31) << 2;
        *(float4*)&Ss[r * AT_S + dq] =
            *(const float4*)&q[(size_t)(n0 + r) * D_ + h * DH_ + dq];
    }
    if (tid < 128) { rowm[tid] = -1e30f; rsum[tid] = 0.0f; }
    __syncthreads();
    // ---- stage 2: transpose Ss -> SqT [d][r] (conflict-free STS) ----
    for (int idx = tid; idx < 128 * 32; idx += 256) {
        const int r = idx & 127, db = (idx >> 7) << 2;
        const float4 v = *(const float4*)&Ss[r * AT_S + db];
        SqT[(db + 0) * AT_S + r] = v.x;
        SqT[(db + 1) * AT_S + r] = v.y;
        SqT[(db + 2) * AT_S + r] = v.z;
        SqT[(db + 3) * AT_S + r] = v.w;
    }

    ull Oa2[8][4] = {};

    for (int t = 0; t < 4; t++) {
        const int m0 = t * 128;
        __syncthreads();
        // ---- K tile: stage 1 row-major into Ss scratch (vectorized) ----
        for (int idx = tid; idx < 128 * 32; idx += 256) {
            const int c = idx >> 5, dq = (idx & 31) << 2;
            *(float4*)&Ss[c * AT_S + dq] =
                *(const float4*)&kv[(size_t)(m0 + c) * (2 * D_) + h * DH_ + dq];
        }
        __syncthreads();
        // ---- stage 2: transpose Ss -> Skv as K^T [d][c] ----
        for (int idx = tid; idx < 128 * 32; idx += 256) {
            const int c = idx & 127, db = (idx >> 7) << 2;
            const float4 v = *(const float4*)&Ss[c * AT_S + db];
            Skv[(db + 0) * AT_S + c] = v.x;
            Skv[(db + 1) * AT_S + c] = v.y;
            Skv[(db + 2) * AT_S + c] = v.z;
            Skv[(db + 3) * AT_S + c] = v.w;
        }
        __syncthreads();

        // ---- scores: S = Q K^T (packed j-pairs) ----
        {
            ull acc2[8][4] = {};
#pragma unroll 2
            for (int d = 0; d < DH_; d++) {
                const float4 qa0 = *(const float4*)&SqT[d * AT_S + ty * 8];
                const float4 qa1 = *(const float4*)&SqT[d * AT_S + ty * 8 + 4];
                const ulonglong2 kb0 = *(const ulonglong2*)&Skv[d * AT_S + tx * 8];
                const ulonglong2 kb1 = *(const ulonglong2*)&Skv[d * AT_S + tx * 8 + 4];
                const ull b2[4] = {kb0.x, kb0.y, kb1.x, kb1.y};
                const ull a2[8] = {bcast2(qa0.x), bcast2(qa0.y), bcast2(qa0.z), bcast2(qa0.w),
                                   bcast2(qa1.x), bcast2(qa1.y), bcast2(qa1.z), bcast2(qa1.w)};
#pragma unroll
                for (int i = 0; i < 8; i++)
#pragma unroll
                    for (int j = 0; j < 4; j++)
                        fma2(acc2[i][j], a2[i], b2[j]);
            }
            const ull sc2 = bcast2(scale);
#pragma unroll
            for (int i = 0; i < 8; i++) {
                ull* sp = (ull*)&Ss[(ty * 8 + i) * AT_S + tx * 8];
#pragma unroll
                for (int j = 0; j < 4; j++)
                    sp[j] = mul2(acc2[i][j], sc2);
            }
        }
        __syncthreads();

        // ---- online softmax over this tile ----
        for (int rr = 0; rr < 16; rr++) {
            const int r = warp * 16 + rr;
            float v0 = Ss[r * AT_S + lane];
            float v1 = Ss[r * AT_S + lane + 32];
            float v2 = Ss[r * AT_S + lane + 64];
            float v3 = Ss[r * AT_S + lane + 96];
            float mx = fmaxf(fmaxf(v0, v1), fmaxf(v2, v3));
#pragma unroll
            for (int off = 16; off; off >>= 1) mx = fmaxf(mx, __shfl_xor_sync(0xffffffffu, mx, off));
            const float oldm = rowm[r];
            const float newm = fmaxf(oldm, mx);
            const float e0 = __expf(v0 - newm);
            const float e1 = __expf(v1 - newm);
            const float e2 = __expf(v2 - newm);
            const float e3 = __expf(v3 - newm);
            Ss[r * AT_S + lane]      = e0;
            Ss[r * AT_S + lane + 32] = e1;
            Ss[r * AT_S + lane + 64] = e2;
            Ss[r * AT_S + lane + 96] = e3;
            float sum = e0 + e1 + e2 + e3;
#pragma unroll
            for (int off = 16; off; off >>= 1) sum += __shfl_xor_sync(0xffffffffu, sum, off);
            if (lane == 0) {
                const float f = __expf(oldm - newm);
                fsc[r] = f;
                rsum[r] = rsum[r] * f + sum;
                rowm[r] = newm;
            }
        }
        __syncthreads();

        // ---- V tile row-major [m][d] (vectorized, conflict-free) ----
        for (int idx = tid; idx < 128 * 32; idx += 256) {
            const int m = idx >> 5, dq = (idx & 31) << 2;
            *(float4*)&Skv[m * AT_S + dq] =
                *(const float4*)&kv[(size_t)(m0 + m) * (2 * D_) + D_ + h * DH_ + dq];
        }
        __syncthreads();

        // ---- rescale O and accumulate P @ V (packed) ----
#pragma unroll
        for (int i = 0; i < 8; i++) {
            const ull f2 = bcast2(fsc[ty * 8 + i]);
#pragma unroll
            for (int j = 0; j < 4; j++)
                Oa2[i][j] = mul2(Oa2[i][j], f2);
        }
#pragma unroll 2
        for (int m = 0; m < 128; m++) {
            ull a2[8];
#pragma unroll
            for (int i = 0; i < 8; i++) a2[i] = bcast2(Ss[(ty * 8 + i) * AT_S + m]);
            const ulonglong2 vb0 = *(const ulonglong2*)&Skv[m * AT_S + tx * 8];
            const ulonglong2 vb1 = *(const ulonglong2*)&Skv[m * AT_S + tx * 8 + 4];
            const ull b2[4] = {vb0.x, vb0.y, vb1.x, vb1.y};
#pragma unroll
            for (int i = 0; i < 8; i++)
#pragma unroll
                for (int j = 0; j < 4; j++)
                    fma2(Oa2[i][j], a2[i], b2[j]);
        }
    }

    // ---- normalize and write out (packed) ----
#pragma unroll
    for (int i = 0; i < 8; i++) {
        const ull inv2 = bcast2(1.0f / rsum[ty * 8 + i]);
        ull* op = (ull*)&o[(size_t)(n0 + ty * 8 + i) * D_ + h * DH_ + tx * 8];
#pragma unroll
        for (int j = 0; j < 4; j++)
            op[j] = mul2(Oa2[i][j], inv2);
    }
}

// ================= launch: batch-pipelined multi-stream DAG =====================
extern "C" void kernel_launch(void* const* d_in, const int* in_sizes, int n_in,
                              void* d_out, int out_size)
{
    const float* x    = (const float*)d_in[0];
    const float* cond = (const float*)d_in[1];
    const float* wq   = (const float*)d_in[2];
    const float* bq   = (const float*)d_in[3];
    const float* wkv  = (const float*)d_in[4];
    const float* bkv  = (const float*)d_in[5];
    const float* wp   = (const float*)d_in[6];
    const float* bp   = (const float*)d_in[7];
    float* out = (float*)d_out;

    void *p_xq, *p_sx, *p_wqq, *p_swq, *p_wpq, *p_swp, *p_oq, *p_so, *p_q, *p_kv, *p_o;
    cudaGetSymbolAddress(&p_xq, g_xq);   cudaGetSymbolAddress(&p_sx, g_sx);
    cudaGetSymbolAddress(&p_wqq, g_wqq); cudaGetSymbolAddress(&p_swq, g_swq);
    cudaGetSymbolAddress(&p_wpq, g_wpq); cudaGetSymbolAddress(&p_swp, g_swp);
    cudaGetSymbolAddress(&p_oq, g_oq);   cudaGetSymbolAddress(&p_so, g_so);
    cudaGetSymbolAddress(&p_q, g_q);     cudaGetSymbolAddress(&p_kv, g_kv);
    cudaGetSymbolAddress(&p_o, g_o);

    int8_t* xq  = (int8_t*)p_xq;   float* sx  = (float*)p_sx;
    int8_t* wqq = (int8_t*)p_wqq;  float* swq = (float*)p_swq;
    int8_t* wpq = (int8_t*)p_wpq;  float* swp = (float*)p_swp;
    int8_t* oq  = (int8_t*)p_oq;   float* so  = (float*)p_so;
    float* qb   = (float*)p_q;     float* kvb = (float*)p_kv;
    float* ob   = (float*)p_o;

    static cudaStream_t sK = nullptr, sB1 = nullptr;
    static cudaEvent_t eFork, eKV0, eKV1, eWQ, eDONE1;
    if (sK == nullptr) {
        cudaStreamCreateWithFlags(&sK,  cudaStreamNonBlocking);
        cudaStreamCreateWithFlags(&sB1, cudaStreamNonBlocking);
        cudaEventCreateWithFlags(&eFork,  cudaEventDisableTiming);
        cudaEventCreateWithFlags(&eKV0,   cudaEventDisableTiming);
        cudaEventCreateWithFlags(&eKV1,   cudaEventDisableTiming);
        cudaEventCreateWithFlags(&eWQ,    cudaEventDisableTiming);
        cudaEventCreateWithFlags(&eDONE1, cudaEventDisableTiming);
    }

    const int attn_smem = ATTN2_FLOATS * sizeof(float);   // ~200 KB
    cudaFuncSetAttribute(attn_flash_kernel, cudaFuncAttributeMaxDynamicSharedMemorySize, attn_smem);

    const size_t XB = (size_t)N_ * D_;
    const size_t KVB = (size_t)M_ * 2 * D_;

    // ---- fork: kv projection (fp32 FFMA2) on side stream ----
    cudaEventRecord(eFork, 0);
    cudaStreamWaitEvent(sK, eFork, 0);
    {
        dim3 grid((2 * D_) / 128, M_ / 128);
        gemm_f32_kernel<<<grid, 256, 0, sK>>>(cond, wkv, bkv, kvb, 2 * D_, D_);
        cudaEventRecord(eKV0, sK);
        gemm_f32_kernel<<<grid, 256, 0, sK>>>(cond + (size_t)M_ * D_, wkv, bkv,
                                              kvb + KVB, 2 * D_, D_);
        cudaEventRecord(eKV1, sK);
    }

    // ---- main: weight quant, then b0 path only ----
    quant_rows_kernel<<<D_, 256>>>(wq, wqq, swq, D_);
    quant_rows_kernel<<<D_, 256>>>(wp, wpq, swp, D_);
    cudaEventRecord(eWQ, 0);
    quant_rows_kernel<<<N_, 256>>>(x, xq, sx, D_);
    {
        dim3 grid(D_ / 128, N_ / 128);
        gemm_s8_imma_kernel<<<grid, 256>>>(xq, wqq, sx, swq, bq, qb, D_, D_);
    }
    // attn(b0) right after qgemm(b0)
    cudaStreamWaitEvent(0, eKV0, 0);
    {
        dim3 grid(N_ / 128, H_);
        attn_flash_kernel<<<grid, 256, attn_smem>>>(qb, kvb, ob);
    }

    // ---- side branch: b1 path (quant+qgemm fill attn(b0) wave tails) ----
    cudaStreamWaitEvent(sB1, eWQ, 0);
    quant_rows_kernel<<<N_, 256, 0, sB1>>>(x + XB, xq + XB, sx + N_, D_);
    {
        dim3 grid(D_ / 128, N_ / 128);
        gemm_s8_imma_kernel<<<grid, 256, 0, sB1>>>(xq + XB, wqq, sx + N_, swq, bq,
                                                   qb + XB, D_, D_);
    }
    cudaStreamWaitEvent(sB1, eKV1, 0);
    {
        dim3 grid(N_ / 128, H_);
        attn_flash_kernel<<<grid, 256, attn_smem, sB1>>>(qb + XB, kvb + KVB, ob + XB);
    }
    quant_rows_kernel<<<N_, 256, 0, sB1>>>(ob + XB, oq + XB, so + N_, D_);
    {
        dim3 grid(D_ / 128, N_ / 128);
        gemm_s8_imma_kernel<<<grid, 256, 0, sB1>>>(oq + XB, wpq, so + N_, swp, bp,
                                                   out + XB, D_, D_);
    }
    cudaEventRecord(eDONE1, sB1);

    // ---- main: epilogue(b0) ----
    quant_rows_kernel<<<N_, 256>>>(ob, oq, so, D_);
    {
        dim3 grid(D_ / 128, N_ / 128);
        gemm_s8_imma_kernel<<<grid, 256>>>(oq, wpq, so, swp, bp, out, D_, D_);
    }

    // ---- join ----
    cudaStreamWaitEvent(0, eDONE1, 0);
}

// round 12
// speedup vs baseline: 1.9413x; 1.0058x over previous
#include <cuda_runtime.h>
#include <cstdint>

#define B_  2
#define N_  4096
#define M_  512
#define D_  2048
#define H_  16
#define DH_ 128

typedef unsigned long long ull;

// ---------------- packed f32x2 helpers (IEEE fp32 per lane, bit-identical) ------
__device__ __forceinline__ ull pack2(float lo, float hi) {
    ull r; asm("mov.b64 %0, {%1, %2};" : "=l"(r) : "f"(lo), "f"(hi)); return r;
}
__device__ __forceinline__ ull bcast2(float v) { return pack2(v, v); }
__device__ __forceinline__ void unpack2(ull v, float& lo, float& hi) {
    asm("mov.b64 {%0, %1}, %2;" : "=f"(lo), "=f"(hi) : "l"(v));
}
__device__ __forceinline__ void fma2(ull& d, ull a, ull b) {
    asm("fma.rn.f32x2 %0, %1, %2, %0;" : "+l"(d) : "l"(a), "l"(b));
}
__device__ __forceinline__ ull mul2(ull a, ull b) {
    ull d; asm("mul.rn.f32x2 %0, %1, %2;" : "=l"(d) : "l"(a), "l"(b)); return d;
}
__device__ __forceinline__ ull add2(ull a, ull b) {
    ull d; asm("add.rn.f32x2 %0, %1, %2;" : "=l"(d) : "l"(a), "l"(b)); return d;
}

// ================= scratch ======================================================
__device__ int8_t g_xq[(size_t)B_ * N_ * D_];
__device__ float  g_sx[B_ * N_];
__device__ int8_t g_wqq[(size_t)D_ * D_];
__device__ float  g_swq[D_];
__device__ int8_t g_wpq[(size_t)D_ * D_];
__device__ float  g_swp[D_];
__device__ int8_t g_oq[(size_t)B_ * N_ * D_];
__device__ float  g_so[B_ * N_];
__device__ float  g_q[(size_t)B_ * N_ * D_];
__device__ float  g_kv[(size_t)B_ * M_ * 2 * D_];
__device__ float  g_o[(size_t)B_ * N_ * D_];

// ================= per-row int8 fake-quant (matches jax _qdq exactly) ===========
__global__ void quant_rows_kernel(const float* __restrict__ in, int8_t* __restrict__ outq,
                                  float* __restrict__ scales, int cols)
{
    const int row = blockIdx.x;
    const float* p = in + (size_t)row * cols;
    __shared__ float red[256];
    float mx = 0.0f;
    for (int c = threadIdx.x * 4; c < cols; c += blockDim.x * 4) {
        float4 v = *(const float4*)&p[c];
        mx = fmaxf(mx, fmaxf(fmaxf(fabsf(v.x), fabsf(v.y)), fmaxf(fabsf(v.z), fabsf(v.w))));
    }
    red[threadIdx.x] = mx;
    __syncthreads();
    for (int s = 128; s > 0; s >>= 1) {
        if (threadIdx.x < s)
            red[threadIdx.x] = fmaxf(red[threadIdx.x], red[threadIdx.x + s]);
        __syncthreads();
    }
    const float sc = fmaxf(red[0] / 127.0f, 1e-8f);
    if (threadIdx.x == 0) scales[row] = sc;
    char4* qo = (char4*)(outq + (size_t)row * cols);
    for (int c = threadIdx.x * 4; c < cols; c += blockDim.x * 4) {
        float4 v = *(const float4*)&p[c];
        char4 q;
        q.x = (int8_t)fminf(127.0f, fmaxf(-127.0f, rintf(v.x / sc)));
        q.y = (int8_t)fminf(127.0f, fmaxf(-127.0f, rintf(v.y / sc)));
        q.z = (int8_t)fminf(127.0f, fmaxf(-127.0f, rintf(v.z / sc)));
        q.w = (int8_t)fminf(127.0f, fmaxf(-127.0f, rintf(v.w / sc)));
        qo[c >> 2] = q;
    }
}

// ================= int8 tensor-core GEMM (mma.sync m16n8k32) ====================
#define ASTRIDE 20

__device__ __forceinline__ void mma_s8(int* c, int a0, int a1, int a2, int a3, int b0, int b1)
{
    asm volatile(
        "mma.sync.aligned.m16n8k32.row.col.s32.s8.s8.s32 "
        "{%0,%1,%2,%3}, {%4,%5,%6,%7}, {%8,%9}, {%0,%1,%2,%3};"
        : "+r"(c[0]), "+r"(c[1]), "+r"(c[2]), "+r"(c[3])
        : "r"(a0), "r"(a1), "r"(a2), "r"(a3), "r"(b0), "r"(b1));
}

__global__ __launch_bounds__(256, 2) void gemm_s8_imma_kernel(
    const int8_t* __restrict__ A, const int8_t* __restrict__ Bm,
    const float* __restrict__ sa, const float* __restrict__ sbv,
    const float* __restrict__ bias, float* __restrict__ C, int colsB, int K)
{
    __shared__ int As[2][128 * ASTRIDE];
    __shared__ int Bs[2][128 * ASTRIDE];
    const int tid = threadIdx.x, lane = tid & 31, wid = tid >> 5;
    const int wm = wid & 1, wn = wid >> 1;
    const int g = lane >> 2, tg = lane & 3;
    const int r0 = blockIdx.y * 128, c0 = blockIdx.x * 128;
    const int Kw = K >> 2;
    const int* Ag = (const int*)A;
    const int* Bg = (const int*)Bm;

    int acc[4][4][4] = {};
    const int ldrow = tid >> 2, ldc4 = (tid & 3) * 4;
    const int nt = K / 64;

    {
        uint4 va0 = *(const uint4*)&Ag[(size_t)(r0 + ldrow) * Kw + ldc4];
        uint4 va1 = *(const uint4*)&Ag[(size_t)(r0 + 64 + ldrow) * Kw + ldc4];
        uint4 vb0 = *(const uint4*)&Bg[(size_t)(c0 + ldrow) * Kw + ldc4];
        uint4 vb1 = *(const uint4*)&Bg[(size_t)(c0 + 64 + ldrow) * Kw + ldc4];
        *(uint4*)&As[0][ldrow * ASTRIDE + ldc4] = va0;
        *(uint4*)&As[0][(64 + ldrow) * ASTRIDE + ldc4] = va1;
        *(uint4*)&Bs[0][ldrow * ASTRIDE + ldc4] = vb0;
        *(uint4*)&Bs[0][(64 + ldrow) * ASTRIDE + ldc4] = vb1;
    }
    __syncthreads();

    for (int t = 0; t < nt; t++) {
        const int buf = t & 1;
        const bool more = (t + 1) < nt;
        uint4 va0, va1, vb0, vb1;
        if (more) {
            const int kw = (t + 1) * 16 + ldc4;
            va0 = *(const uint4*)&Ag[(size_t)(r0 + ldrow) * Kw + kw];
            va1 = *(const uint4*)&Ag[(size_t)(r0 + 64 + ldrow) * Kw + kw];
            vb0 = *(const uint4*)&Bg[(size_t)(c0 + ldrow) * Kw + kw];
            vb1 = *(const uint4*)&Bg[(size_t)(c0 + 64 + ldrow) * Kw + kw];
        }
#pragma unroll
        for (int ks = 0; ks < 2; ks++) {
            const int kw = ks * 8;
            int bf[4][2];
#pragma unroll
            for (int n = 0; n < 4; n++) {
                const int col = wn * 32 + n * 8 + g;
                bf[n][0] = Bs[buf][col * ASTRIDE + kw + tg];
                bf[n][1] = Bs[buf][col * ASTRIDE + kw + tg + 4];
            }
#pragma unroll
            for (int m = 0; m < 4; m++) {
                const int row = wm * 64 + m * 16;
                const int a0 = As[buf][(row + g) * ASTRIDE + kw + tg];
                const int a1 = As[buf][(row + 8 + g) * ASTRIDE + kw + tg];
                const int a2 = As[buf][(row + g) * ASTRIDE + kw + tg + 4];
                const int a3 = As[buf][(row + 8 + g) * ASTRIDE + kw + tg + 4];
#pragma unroll
                for (int n = 0; n < 4; n++)
                    mma_s8(acc[m][n], a0, a1, a2, a3, bf[n][0], bf[n][1]);
            }
        }
        __syncthreads();
        if (more) {
            *(uint4*)&As[buf ^ 1][ldrow * ASTRIDE + ldc4] = va0;
            *(uint4*)&As[buf ^ 1][(64 + ldrow) * ASTRIDE + ldc4] = va1;
            *(uint4*)&Bs[buf ^ 1][ldrow * ASTRIDE + ldc4] = vb0;
            *(uint4*)&Bs[buf ^ 1][(64 + ldrow) * ASTRIDE + ldc4] = vb1;
            __syncthreads();
        }
    }

#pragma unroll
    for (int m = 0; m < 4; m++) {
#pragma unroll
        for (int half = 0; half < 2; half++) {
            const int r = r0 + wm * 64 + m * 16 + g + half * 8;
            const float sr = sa[r];
#pragma unroll
            for (int n = 0; n < 4; n++) {
                const int c = c0 + wn * 32 + n * 8 + tg * 2;
                float2 v;
                v.x = (float)acc[m][n][half * 2 + 0] * sr * sbv[c] + bias[c];
                v.y = (float)acc[m][n][half * 2 + 1] * sr * sbv[c + 1] + bias[c + 1];
                *(float2*)&C[(size_t)r * colsB + c] = v;
            }
        }
    }
}

// ================= fp32 GEMM (kv projection) — packed FFMA2 =====================
__global__ void gemm_f32_kernel(const float* __restrict__ A, const float* __restrict__ Bm,
                                const float* __restrict__ bias, float* __restrict__ C,
                                int colsB, int K)
{
    __shared__ float As[128][17];
    __shared__ float BsT[16][132];
    const int tid = threadIdx.x;
    const int tx = tid & 15, ty = tid >> 4;
    const int r0 = blockIdx.y * 128;
    const int c0 = blockIdx.x * 128;
    ull acc2[8][4] = {};
    for (int kc = 0; kc < K; kc += 16) {
#pragma unroll
        for (int l = 0; l < 8; l++) {
            int idx = tid + l * 256;
            int r = idx >> 4, c = idx & 15;
            As[r][c] = A[(size_t)(r0 + r) * K + kc + c];
            BsT[c][r] = Bm[(size_t)(c0 + r) * K + kc + c];
        }
        __syncthreads();
#pragma unroll
        for (int kk = 0; kk < 16; kk++) {
            const ulonglong2 bl0 = *(const ulonglong2*)&BsT[kk][tx * 8];
            const ulonglong2 bl1 = *(const ulonglong2*)&BsT[kk][tx * 8 + 4];
            const ull b2[4] = {bl0.x, bl0.y, bl1.x, bl1.y};
            ull a2[8];
#pragma unroll
            for (int i = 0; i < 8; i++) a2[i] = bcast2(As[ty * 8 + i][kk]);
#pragma unroll
            for (int i = 0; i < 8; i++)
#pragma unroll
                for (int j = 0; j < 4; j++)
                    fma2(acc2[i][j], a2[i], b2[j]);
        }
        __syncthreads();
    }
    const ull bias2[4] = {
        *(const ull*)&bias[c0 + tx * 8],     *(const ull*)&bias[c0 + tx * 8 + 2],
        *(const ull*)&bias[c0 + tx * 8 + 4], *(const ull*)&bias[c0 + tx * 8 + 6]};
#pragma unroll
    for (int i = 0; i < 8; i++) {
        const int r = r0 + ty * 8 + i;
        ull* cp = (ull*)&C[(size_t)r * colsB + c0 + tx * 8];
#pragma unroll
        for (int j = 0; j < 4; j++)
            cp[j] = add2(acc2[i][j], bias2[j]);
    }
}

// ================= flash attention — small-smem (136KB) FFMA2 version ===========
// grid (N/128, H), 256 threads. K/V tiles of 64. Per-batch pointers.
// smem layout (floats): SqT[128][132] | Skv(max(K^T 128x68, V 64x132)) | Ss/scratch | state
#define AT_QS 132
#define AT_KS 68
#define AT_VS 132
#define AT_SC 132      // scratch stride: MUST be multiple of 4 for float4 alignment
#define OFF_SKV 16896
#define OFF_SS  (16896 + 8704)
#define OFF_ST  (16896 + 8704 + 8704)
#define ATTN2_FLOATS (16896 + 8704 + 8704 + 384)

__global__ __launch_bounds__(256) void attn_flash_kernel(
    const float* __restrict__ q, const float* __restrict__ kv, float* __restrict__ o)
{
    extern __shared__ float sm[];
    float* SqT  = sm;               // Q^T [d][r] (128x132)
    float* Skv  = sm + OFF_SKV;     // K^T [d][c] (128x68)  OR  V [m][d] (64x132)
    float* Ssc  = sm + OFF_SS;      // transpose scratch (64x132) / scores P (128x68)
    float* rowm = sm + OFF_ST;
    float* rsum = rowm + 128;
    float* fsc  = rowm + 256;

    const int h = blockIdx.y, n0 = blockIdx.x * 128;
    const int tid = threadIdx.x;
    const int tx = tid & 15, ty = tid >> 4;       // 16x16 grid (S rows / PV both)
    const float scale = 0.08838834764831845f;     // 1/sqrt(128)

    // ---- Q transpose in two halves via Ssc scratch ----
#pragma unroll
    for (int hf = 0; hf < 2; hf++) {
        for (int idx = tid; idx < 64 * 32; idx += 256) {
            const int r = idx >> 5, dq = (idx & 31) << 2;
            *(float4*)&Ssc[r * AT_SC + dq] =
                *(const float4*)&q[(size_t)(n0 + hf * 64 + r) * D_ + h * DH_ + dq];
        }
        __syncthreads();
        for (int idx = tid; idx < 64 * 32; idx += 256) {
            const int r = idx & 63, db = (idx >> 6) << 2;
            const float4 v = *(const float4*)&Ssc[r * AT_SC + db];
            SqT[(db + 0) * AT_QS + hf * 64 + r] = v.x;
            SqT[(db + 1) * AT_QS + hf * 64 + r] = v.y;
            SqT[(db + 2) * AT_QS + hf * 64 + r] = v.z;
            SqT[(db + 3) * AT_QS + hf * 64 + r] = v.w;
        }
        __syncthreads();
    }
    if (tid < 128) { rowm[tid] = -1e30f; rsum[tid] = 0.0f; }

    ull Oa2[8][4] = {};

    for (int t = 0; t < 8; t++) {
        const int m0 = t * 64;
        __syncthreads();   // prior PV done reading Ssc/Skv

        // ---- K tile stage 1: row-major into Ssc [64][132] ----
        for (int idx = tid; idx < 64 * 32; idx += 256) {
            const int c = idx >> 5, dq = (idx & 31) << 2;
            *(float4*)&Ssc[c * AT_SC + dq] =
                *(const float4*)&kv[(size_t)(m0 + c) * (2 * D_) + h * DH_ + dq];
        }
        __syncthreads();
        // ---- stage 2: transpose -> Skv as K^T [d][c] (128x68) ----
        for (int idx = tid; idx < 64 * 32; idx += 256) {
            const int c = idx & 63, db = (idx >> 6) << 2;
            const float4 v = *(const float4*)&Ssc[c * AT_SC + db];
            Skv[(db + 0) * AT_KS + c] = v.x;
            Skv[(db + 1) * AT_KS + c] = v.y;
            Skv[(db + 2) * AT_KS + c] = v.z;
            Skv[(db + 3) * AT_KS + c] = v.w;
        }
        __syncthreads();

        // ---- S = Q K^T : output [128][64]; thread: 4 row-pairs x 4 cols ----
        {
            ull acc2[4][4] = {};   // [rowpair][col], pair packed along ROWS (LDS.64, no MOV)
#pragma unroll 4
            for (int d = 0; d < DH_; d++) {
                ull a2[4];
#pragma unroll
                for (int p = 0; p < 4; p++)
                    a2[p] = *(const ull*)&SqT[d * AT_QS + ty * 8 + 2 * p];
                ull b2[4];
#pragma unroll
                for (int c = 0; c < 4; c++)
                    b2[c] = bcast2(Skv[d * AT_KS + tx * 4 + c]);
#pragma unroll
                for (int p = 0; p < 4; p++)
#pragma unroll
                    for (int c = 0; c < 4; c++)
                        fma2(acc2[p][c], a2[p], b2[c]);
            }
            const ull sc2 = bcast2(scale);
#pragma unroll
            for (int p = 0; p < 4; p++) {
#pragma unroll
                for (int c = 0; c < 4; c++) {
                    float lo, hi;
                    unpack2(mul2(acc2[p][c], sc2), lo, hi);
                    Ssc[(ty * 8 + 2 * p + 0) * AT_KS + tx * 4 + c] = lo;
                    Ssc[(ty * 8 + 2 * p + 1) * AT_KS + tx * 4 + c] = hi;
                }
            }
        }
        __syncthreads();

        // ---- V tile load (row-major [m][d]) + row-pair softmax, one phase ----
        for (int idx = tid; idx < 64 * 32; idx += 256) {
            const int m = idx >> 5, dq = (idx & 31) << 2;
            *(float4*)&Skv[m * AT_VS + dq] =
                *(const float4*)&kv[(size_t)(m0 + m) * (2 * D_) + D_ + h * DH_ + dq];
        }
        {
            const int r = tid >> 1, hf = tid & 1;
            float* rowp = &Ssc[r * AT_KS + hf * 32];
            float4 v[8];
#pragma unroll
            for (int i = 0; i < 8; i++) v[i] = *(const float4*)&rowp[i * 4];
            float mx = -1e30f;
#pragma unroll
            for (int i = 0; i < 8; i++)
                mx = fmaxf(mx, fmaxf(fmaxf(v[i].x, v[i].y), fmaxf(v[i].z, v[i].w)));
            mx = fmaxf(mx, __shfl_xor_sync(0xffffffffu, mx, 1));
            const float oldm = rowm[r];
            const float newm = fmaxf(oldm, mx);
            float sum = 0.0f;
#pragma unroll
            for (int i = 0; i < 8; i++) {
                v[i].x = __expf(v[i].x - newm);
                v[i].y = __expf(v[i].y - newm);
                v[i].z = __expf(v[i].z - newm);
                v[i].w = __expf(v[i].w - newm);
                sum += (v[i].x + v[i].y) + (v[i].z + v[i].w);
                *(float4*)&rowp[i * 4] = v[i];
            }
            sum += __shfl_xor_sync(0xffffffffu, sum, 1);
            if (hf == 0) {
                const float f = __expf(oldm - newm);
                fsc[r] = f;
                rsum[r] = rsum[r] * f + sum;
                rowm[r] = newm;
            }
        }
        __syncthreads();

        // ---- rescale O, accumulate P @ V over this 64-tile ----
#pragma unroll
        for (int i = 0; i < 8; i++) {
            const ull f2 = bcast2(fsc[ty * 8 + i]);
#pragma unroll
            for (int j = 0; j < 4; j++)
                Oa2[i][j] = mul2(Oa2[i][j], f2);
        }
#pragma unroll 2
        for (int m = 0; m < 64; m++) {
            ull a2[8];
#pragma unroll
            for (int i = 0; i < 8; i++) a2[i] = bcast2(Ssc[(ty * 8 + i) * AT_KS + m]);
            const ulonglong2 vb0 = *(const ulonglong2*)&Skv[m * AT_VS + tx * 8];
            const ulonglong2 vb1 = *(const ulonglong2*)&Skv[m * AT_VS + tx * 8 + 4];
            const ull b2[4] = {vb0.x, vb0.y, vb1.x, vb1.y};
#pragma unroll
            for (int i = 0; i < 8; i++)
#pragma unroll
                for (int j = 0; j < 4; j++)
                    fma2(Oa2[i][j], a2[i], b2[j]);
        }
    }

    // ---- normalize and write out (packed) ----
#pragma unroll
    for (int i = 0; i < 8; i++) {
        const ull inv2 = bcast2(1.0f / rsum[ty * 8 + i]);
        ull* op = (ull*)&o[(size_t)(n0 + ty * 8 + i) * D_ + h * DH_ + tx * 8];
#pragma unroll
        for (int j = 0; j < 4; j++)
            op[j] = mul2(Oa2[i][j], inv2);
    }
}

// ================= launch: batch-pipelined multi-stream DAG =====================
extern "C" void kernel_launch(void* const* d_in, const int* in_sizes, int n_in,
                              void* d_out, int out_size)
{
    const float* x    = (const float*)d_in[0];
    const float* cond = (const float*)d_in[1];
    const float* wq   = (const float*)d_in[2];
    const float* bq   = (const float*)d_in[3];
    const float* wkv  = (const float*)d_in[4];
    const float* bkv  = (const float*)d_in[5];
    const float* wp   = (const float*)d_in[6];
    const float* bp   = (const float*)d_in[7];
    float* out = (float*)d_out;

    void *p_xq, *p_sx, *p_wqq, *p_swq, *p_wpq, *p_swp, *p_oq, *p_so, *p_q, *p_kv, *p_o;
    cudaGetSymbolAddress(&p_xq, g_xq);   cudaGetSymbolAddress(&p_sx, g_sx);
    cudaGetSymbolAddress(&p_wqq, g_wqq); cudaGetSymbolAddress(&p_swq, g_swq);
    cudaGetSymbolAddress(&p_wpq, g_wpq); cudaGetSymbolAddress(&p_swp, g_swp);
    cudaGetSymbolAddress(&p_oq, g_oq);   cudaGetSymbolAddress(&p_so, g_so);
    cudaGetSymbolAddress(&p_q, g_q);     cudaGetSymbolAddress(&p_kv, g_kv);
    cudaGetSymbolAddress(&p_o, g_o);

    int8_t* xq  = (int8_t*)p_xq;   float* sx  = (float*)p_sx;
    int8_t* wqq = (int8_t*)p_wqq;  float* swq = (float*)p_swq;
    int8_t* wpq = (int8_t*)p_wpq;  float* swp = (float*)p_swp;
    int8_t* oq  = (int8_t*)p_oq;   float* so  = (float*)p_so;
    float* qb   = (float*)p_q;     float* kvb = (float*)p_kv;
    float* ob   = (float*)p_o;

    static cudaStream_t sK = nullptr, sB1 = nullptr;
    static cudaEvent_t eFork, eKV0, eKV1, eWQ, eDONE1;
    if (sK == nullptr) {
        cudaStreamCreateWithFlags(&sK,  cudaStreamNonBlocking);
        cudaStreamCreateWithFlags(&sB1, cudaStreamNonBlocking);
        cudaEventCreateWithFlags(&eFork,  cudaEventDisableTiming);
        cudaEventCreateWithFlags(&eKV0,   cudaEventDisableTiming);
        cudaEventCreateWithFlags(&eKV1,   cudaEventDisableTiming);
        cudaEventCreateWithFlags(&eWQ,    cudaEventDisableTiming);
        cudaEventCreateWithFlags(&eDONE1, cudaEventDisableTiming);
    }

    const int attn_smem = ATTN2_FLOATS * sizeof(float);   // ~136 KB
    cudaFuncSetAttribute(attn_flash_kernel, cudaFuncAttributeMaxDynamicSharedMemorySize, attn_smem);

    const size_t XB = (size_t)N_ * D_;
    const size_t KVB = (size_t)M_ * 2 * D_;

    // ---- fork: kv projection (fp32 FFMA2) on side stream ----
    cudaEventRecord(eFork, 0);
    cudaStreamWaitEvent(sK, eFork, 0);
    {
        dim3 grid((2 * D_) / 128, M_ / 128);
        gemm_f32_kernel<<<grid, 256, 0, sK>>>(cond, wkv, bkv, kvb, 2 * D_, D_);
        cudaEventRecord(eKV0, sK);
        gemm_f32_kernel<<<grid, 256, 0, sK>>>(cond + (size_t)M_ * D_, wkv, bkv,
                                              kvb + KVB, 2 * D_, D_);
        cudaEventRecord(eKV1, sK);
    }

    // ---- main: weight quant, then b0 path ----
    quant_rows_kernel<<<D_, 256>>>(wq, wqq, swq, D_);
    quant_rows_kernel<<<D_, 256>>>(wp, wpq, swp, D_);
    cudaEventRecord(eWQ, 0);
    quant_rows_kernel<<<N_, 256>>>(x, xq, sx, D_);
    {
        dim3 grid(D_ / 128, N_ / 128);
        gemm_s8_imma_kernel<<<grid, 256>>>(xq, wqq, sx, swq, bq, qb, D_, D_);
    }
    cudaStreamWaitEvent(0, eKV0, 0);
    {
        dim3 grid(N_ / 128, H_);
        attn_flash_kernel<<<grid, 256, attn_smem>>>(qb, kvb, ob);
    }

    // ---- side branch: b1 path (tensor-pipe work overlaps attn(b0)) ----
    cudaStreamWaitEvent(sB1, eWQ, 0);
    quant_rows_kernel<<<N_, 256, 0, sB1>>>(x + XB, xq + XB, sx + N_, D_);
    {
        dim3 grid(D_ / 128, N_ / 128);
        gemm_s8_imma_kernel<<<grid, 256, 0, sB1>>>(xq + XB, wqq, sx + N_, swq, bq,
                                                   qb + XB, D_, D_);
    }
    cudaStreamWaitEvent(sB1, eKV1, 0);
    {
        dim3 grid(N_ / 128, H_);
        attn_flash_kernel<<<grid, 256, attn_smem, sB1>>>(qb + XB, kvb + KVB, ob + XB);
    }
    quant_rows_kernel<<<N_, 256, 0, sB1>>>(ob + XB, oq + XB, so + N_, D_);
    {
        dim3 grid(D_ / 128, N_ / 128);
        gemm_s8_imma_kernel<<<grid, 256, 0, sB1>>>(oq + XB, wpq, so + N_, swp, bp,
                                                   out + XB, D_, D_);
    }
    cudaEventRecord(eDONE1, sB1);

    // ---- main: epilogue(b0) (tensor pipe, overlaps attn(b1)) ----
    quant_rows_kernel<<<N_, 256>>>(ob, oq, so, D_);
    {
        dim3 grid(D_ / 128, N_ / 128);
        gemm_s8_imma_kernel<<<grid, 256>>>(oq, wpq, so, swp, bp, out, D_, D_);
    }

    // ---- join ----
    cudaStreamWaitEvent(0, eDONE1, 0);
}